// round 13
// baseline (speedup 1.0000x reference)
#include <cuda_runtime.h>
#include <cuda_bf16.h>
#include <cstdint>

#define NN 50000
#define EE 800000
#define REGSZ (NN * 128)
#define CHUNK 512
#define NCHUNK ((NN + CHUNK - 1) / CHUNK)   // 98

// ---------------- scratch (static device globals; no runtime alloc) ----------
__device__ int   g_deg[4 * NN];
__device__ int   g_cursor[4 * NN];
__device__ int   g_rowptr[4 * (NN + 1)];
__device__ float g_dinv[4 * NN];
__device__ int   g_csr_src[4 * EE];
__device__ float g_csr_coef[4 * EE];
__device__ int   g_is64[4];
__device__ int   g_chunksum[4 * NCHUNK];
__device__ int   g_chunkoff[4 * NCHUNK];
// per-pipeline intermediates (4 concurrent pipelines, all fp32 now)
__device__ float g_xw1[4][NN * 256];
__device__ float g_h[4][NN * 256];
__device__ float g_xw2[4][NN * 128];
// weights transposed [n][k], bf16 hi/lo split
#define WOFF1(p) ((p) * 65536)
#define WOFF2(p) (262144 + (p) * 32768)
#define WOFFR(i) (393216 + (i) * 32768)
__device__ __nv_bfloat16 g_Whi[458752];
__device__ __nv_bfloat16 g_Wlo[458752];

// ---------------- mma.sync / cp.async helpers --------------------------------
__device__ __forceinline__ uint32_t smem_u32(const void* p) {
    uint32_t a;
    asm("{ .reg .u64 t; cvta.to.shared.u64 t, %1; cvt.u32.u64 %0, t; }" : "=r"(a) : "l"(p));
    return a;
}
__device__ __forceinline__ void ldsm4(uint32_t& r0, uint32_t& r1, uint32_t& r2, uint32_t& r3,
                                      uint32_t a) {
    asm volatile("ldmatrix.sync.aligned.m8n8.x4.shared.b16 {%0,%1,%2,%3}, [%4];"
                 : "=r"(r0), "=r"(r1), "=r"(r2), "=r"(r3) : "r"(a));
}
__device__ __forceinline__ void mma16816(float* d, const uint32_t* a, const uint32_t* b) {
    asm volatile(
        "mma.sync.aligned.m16n8k16.row.col.f32.bf16.bf16.f32 "
        "{%0,%1,%2,%3}, {%4,%5,%6,%7}, {%8,%9}, {%0,%1,%2,%3};"
        : "+f"(d[0]), "+f"(d[1]), "+f"(d[2]), "+f"(d[3])
        : "r"(a[0]), "r"(a[1]), "r"(a[2]), "r"(a[3]), "r"(b[0]), "r"(b[1]));
}
__device__ __forceinline__ void cp16(uint32_t dst, const void* src) {
    asm volatile("cp.async.ca.shared.global [%0], [%1], 16;"
                 :: "r"(dst), "l"(src) : "memory");
}
#define CP_COMMIT() asm volatile("cp.async.commit_group;" ::: "memory")

__device__ __forceinline__ uint32_t pack_bf2(float x, float y) {
    __nv_bfloat162 v(__float2bfloat16(x), __float2bfloat16(y));
    return *reinterpret_cast<uint32_t*>(&v);
}
// fp32x4 -> bf16 hi pair (2x u32) + lo pair (2x u32)
__device__ __forceinline__ void cvt4(float4 f, uint32_t& h0, uint32_t& h1,
                                     uint32_t& l0, uint32_t& l1) {
    __nv_bfloat16 a = __float2bfloat16(f.x), b = __float2bfloat16(f.y);
    __nv_bfloat16 c = __float2bfloat16(f.z), d = __float2bfloat16(f.w);
    __nv_bfloat162 hA(a, b), hB(c, d);
    h0 = *reinterpret_cast<uint32_t*>(&hA);
    h1 = *reinterpret_cast<uint32_t*>(&hB);
    l0 = pack_bf2(f.x - __bfloat162float(a), f.y - __bfloat162float(b));
    l1 = pack_bf2(f.z - __bfloat162float(c), f.w - __bfloat162float(d));
}

// ---------------- edge dtype sniffing + decode -------------------------------
__global__ void detect_kernel(const void* e0, const void* e1, const void* e2, const void* e3) {
    if (threadIdx.x < 4) {
        const void* p = threadIdx.x == 0 ? e0 : threadIdx.x == 1 ? e1 : threadIdx.x == 2 ? e2 : e3;
        const unsigned int* u = (const unsigned int*)p;
        unsigned int acc = 0;
        for (int i = 0; i < 64; i++) acc |= u[2 * i + 1];
        g_is64[threadIdx.x] = (acc == 0) ? 1 : 0;
    }
}

__device__ __forceinline__ int2 load_edge(const void* ep, int is64, int e) {
    int s, d;
    if (is64) {
        const long long* p = (const long long*)ep;
        s = (int)p[e];
        d = (int)p[EE + e];
    } else {
        const int* p = (const int*)ep;
        s = p[e];
        d = p[EE + e];
    }
    return make_int2(s, d);
}

// ---------------- CSR build ---------------------------------------------------
__global__ void zero_counts() {
    int i = blockIdx.x * blockDim.x + threadIdx.x;
    if (i < 4 * NN) { g_deg[i] = 0; g_cursor[i] = 0; }
}

__global__ void build_deg(const void* e0, const void* e1, const void* e2, const void* e3) {
    int e = blockIdx.x * blockDim.x + threadIdx.x;
    int r = blockIdx.y;
    if (e >= EE) return;
    const void* ep = r == 0 ? e0 : r == 1 ? e1 : r == 2 ? e2 : e3;
    int2 sd = load_edge(ep, g_is64[r], e);
    atomicAdd(&g_deg[r * NN + sd.y], 1);
}

__global__ void calc_dinv() {
    int i = blockIdx.x * blockDim.x + threadIdx.x;
    if (i < 4 * NN) g_dinv[i] = rsqrtf((float)g_deg[i] + 1.0f);
}

__global__ void scan_p1() {
    int r = blockIdx.y;
    int i = blockIdx.x * CHUNK + threadIdx.x;
    int v = (i < NN) ? g_deg[r * NN + i] : 0;
    __shared__ int sh[CHUNK];
    sh[threadIdx.x] = v;
    __syncthreads();
    for (int off = CHUNK / 2; off > 0; off >>= 1) {
        if (threadIdx.x < off) sh[threadIdx.x] += sh[threadIdx.x + off];
        __syncthreads();
    }
    if (threadIdx.x == 0) g_chunksum[r * NCHUNK + blockIdx.x] = sh[0];
}

__global__ void scan_p2() {
    int r = blockIdx.x;
    __shared__ int sh[128];
    int v = (threadIdx.x < NCHUNK) ? g_chunksum[r * NCHUNK + threadIdx.x] : 0;
    sh[threadIdx.x] = v;
    __syncthreads();
    for (int off = 1; off < 128; off <<= 1) {
        int t = (threadIdx.x >= off) ? sh[threadIdx.x - off] : 0;
        __syncthreads();
        sh[threadIdx.x] += t;
        __syncthreads();
    }
    if (threadIdx.x < NCHUNK) g_chunkoff[r * NCHUNK + threadIdx.x] = sh[threadIdx.x] - v;
    if (threadIdx.x == 127) g_rowptr[r * (NN + 1) + NN] = sh[127];
}

__global__ void scan_p3() {
    int r = blockIdx.y;
    int i = blockIdx.x * CHUNK + threadIdx.x;
    int v = (i < NN) ? g_deg[r * NN + i] : 0;
    __shared__ int sh[CHUNK];
    sh[threadIdx.x] = v;
    __syncthreads();
    for (int off = 1; off < CHUNK; off <<= 1) {
        int t = (threadIdx.x >= off) ? sh[threadIdx.x - off] : 0;
        __syncthreads();
        sh[threadIdx.x] += t;
        __syncthreads();
    }
    if (i < NN)
        g_rowptr[r * (NN + 1) + i] = g_chunkoff[r * NCHUNK + blockIdx.x] + sh[threadIdx.x] - v;
}

__global__ void build_csr(const void* e0, const void* e1, const void* e2, const void* e3) {
    int e = blockIdx.x * blockDim.x + threadIdx.x;
    int r = blockIdx.y;
    if (e >= EE) return;
    const void* ep = r == 0 ? e0 : r == 1 ? e1 : r == 2 ? e2 : e3;
    int2 sd = load_edge(ep, g_is64[r], e);
    int pos = g_rowptr[r * (NN + 1) + sd.y] + atomicAdd(&g_cursor[r * NN + sd.y], 1);
    g_csr_src[r * EE + pos] = sd.x;
    g_csr_coef[r * EE + pos] = g_dinv[r * NN + sd.x] * g_dinv[r * NN + sd.y];
}

// ---------------- weight conversion (batched, tiny) ---------------------------
struct WArgs {
    const float* W[10];
    int N[10];
    int off[10];
};
__global__ void convW10(WArgs a, __nv_bfloat16* __restrict__ hi, __nv_bfloat16* __restrict__ lo) {
    int m = blockIdx.y;
    int i = blockIdx.x * 256 + threadIdx.x;
    int N = a.N[m];
    if (i >= N * 256) return;
    int n = i >> 8, k = i & 255;
    float v = a.W[m][k * N + n];
    __nv_bfloat16 h = __float2bfloat16(v);
    hi[a.off[m] + i] = h;
    lo[a.off[m] + i] = __float2bfloat16(v - __bfloat162float(h));
}

// ---------------- GEMM: C[M,Ntot] = A(fp32) @ Wt^T, in-kernel bf16 split ------
// A staged via LDG.128 fp32 + convert (2-stage ring); B via cp.async (3-stage)
#define KC 32
#define LDA 40
#define ABUF_E (2 * 128 * LDA)              // 10240 elems per A stage (hi+lo)
#define BSTG_E (2 * 64 * LDA)               // 5120 elems per B stage (hi+lo)
#define B_BASE (2 * ABUF_E)                 // 20480
#define SMB_GEMM ((2 * ABUF_E + 3 * BSTG_E) * 2)   // 71680 B

__global__ void __launch_bounds__(256, 2) gemm_mma(
    const float* __restrict__ A,
    const __nv_bfloat16* __restrict__ Bhi, const __nv_bfloat16* __restrict__ Blo,
    float* __restrict__ C, int M, int Ntot,
    const float* __restrict__ bias, int addbias) {
    extern __shared__ __nv_bfloat16 sm[];
    uint32_t sb = smem_u32(sm);
    int tid = threadIdx.x, lane = tid & 31, w = tid >> 5;
    int wm = w & 3, wn = w >> 2;            // 4 warps M x 2 warps N
    int m0 = blockIdx.y * 128, n0 = blockIdx.x * 64;

    float acc[2][4][4];
#pragma unroll
    for (int mi = 0; mi < 2; mi++)
#pragma unroll
        for (int ni = 0; ni < 4; ni++)
#pragma unroll
            for (int q = 0; q < 4; q++) acc[mi][ni][q] = 0.0f;

    // A staging: thread -> (row, 16-col group)
    int a_row = tid >> 1;                 // 0..127
    int a_colg = (tid & 1) * 16;          // 0 or 16
    bool a_ok = (m0 + a_row) < M;
    const float* a_src = &A[(size_t)(a_ok ? (m0 + a_row) : (M - 1)) * 256 + a_colg];
    int a_e = a_row * LDA + a_colg;       // elem offset within stage (hi region)

    // B staging: thread -> (row 0..63, 8-col group)
    int b_row = tid >> 2;
    int b_col = (tid & 3) * 8;

    // ldmatrix fragment offsets
    uint32_t a_off[2], b_off[2];
#pragma unroll
    for (int mi = 0; mi < 2; mi++)
        a_off[mi] = (uint32_t)((wm * 32 + mi * 16 + (lane & 15)) * LDA + (lane >> 4) * 8);
#pragma unroll
    for (int bt = 0; bt < 2; bt++)
        b_off[bt] = (uint32_t)((wn * 32 + bt * 16 + ((lane >> 4) << 3) + (lane & 7)) * LDA +
                               ((lane >> 3) & 1) * 8);

    float4 rA[4];
    auto ldgA = [&](int c) {
        if (a_ok) {
            const float4* s = (const float4*)(a_src + c * KC);
            rA[0] = s[0]; rA[1] = s[1]; rA[2] = s[2]; rA[3] = s[3];
        } else {
            rA[0] = rA[1] = rA[2] = rA[3] = make_float4(0.f, 0.f, 0.f, 0.f);
        }
    };
    auto stsA = [&](int buf) {
        uint32_t h[8], l[8];
        cvt4(rA[0], h[0], h[1], l[0], l[1]);
        cvt4(rA[1], h[2], h[3], l[2], l[3]);
        cvt4(rA[2], h[4], h[5], l[4], l[5]);
        cvt4(rA[3], h[6], h[7], l[6], l[7]);
        int base = buf * ABUF_E;
        *(uint4*)&sm[base + a_e] = make_uint4(h[0], h[1], h[2], h[3]);
        *(uint4*)&sm[base + a_e + 8] = make_uint4(h[4], h[5], h[6], h[7]);
        *(uint4*)&sm[base + 128 * LDA + a_e] = make_uint4(l[0], l[1], l[2], l[3]);
        *(uint4*)&sm[base + 128 * LDA + a_e + 8] = make_uint4(l[4], l[5], l[6], l[7]);
    };
    auto cpB = [&](int c) {
        uint32_t base = sb + (uint32_t)((B_BASE + (c % 3) * BSTG_E) * 2);
        cp16(base + (uint32_t)((b_row * LDA + b_col) * 2),
             &Bhi[(size_t)(n0 + b_row) * 256 + c * KC + b_col]);
        cp16(base + (uint32_t)((64 * LDA + b_row * LDA + b_col) * 2),
             &Blo[(size_t)(n0 + b_row) * 256 + c * KC + b_col]);
        CP_COMMIT();
    };

    // prologue
    ldgA(0); cpB(0);
    stsA(0);
    ldgA(1); cpB(1);

#pragma unroll
    for (int c = 0; c < 8; c++) {
        if (c < 7) asm volatile("cp.async.wait_group 1;" ::: "memory");
        else       asm volatile("cp.async.wait_group 0;" ::: "memory");
        __syncthreads();
        if (c + 1 < 8) stsA((c + 1) & 1);
        if (c + 2 < 8) { ldgA(c + 2); cpB(c + 2); }

        uint32_t sbA = sb + (uint32_t)(((c & 1) * ABUF_E) * 2);
        uint32_t sbB = sb + (uint32_t)((B_BASE + (c % 3) * BSTG_E) * 2);
#pragma unroll
        for (int ks = 0; ks < 2; ks++) {
            int k = ks * 16;
            uint32_t aH[2][4], aL[2][4], bH[4][2], bL[4][2];
#pragma unroll
            for (int mi = 0; mi < 2; mi++) {
                ldsm4(aH[mi][0], aH[mi][1], aH[mi][2], aH[mi][3],
                      sbA + ((a_off[mi] + k) << 1));
                ldsm4(aL[mi][0], aL[mi][1], aL[mi][2], aL[mi][3],
                      sbA + ((128 * LDA + a_off[mi] + k) << 1));
            }
#pragma unroll
            for (int bt = 0; bt < 2; bt++) {
                uint32_t r0, r1, r2, r3;
                ldsm4(r0, r1, r2, r3, sbB + ((b_off[bt] + k) << 1));
                bH[bt * 2][0] = r0; bH[bt * 2][1] = r1;
                bH[bt * 2 + 1][0] = r2; bH[bt * 2 + 1][1] = r3;
                ldsm4(r0, r1, r2, r3, sbB + ((64 * LDA + b_off[bt] + k) << 1));
                bL[bt * 2][0] = r0; bL[bt * 2][1] = r1;
                bL[bt * 2 + 1][0] = r2; bL[bt * 2 + 1][1] = r3;
            }
#pragma unroll
            for (int mi = 0; mi < 2; mi++)
#pragma unroll
                for (int ni = 0; ni < 4; ni++) {
                    mma16816(acc[mi][ni], aH[mi], bH[ni]);
                    mma16816(acc[mi][ni], aH[mi], bL[ni]);
                    mma16816(acc[mi][ni], aL[mi], bH[ni]);
                }
        }
        __syncthreads();
    }

    // epilogue
#pragma unroll
    for (int mi = 0; mi < 2; mi++) {
#pragma unroll
        for (int ni = 0; ni < 4; ni++) {
            int col = n0 + wn * 32 + ni * 8 + (lane & 3) * 2;
            int r_lo = m0 + wm * 32 + mi * 16 + (lane >> 2);
            int r_hi = r_lo + 8;
#pragma unroll
            for (int half = 0; half < 2; half++) {
                int row = half ? r_hi : r_lo;
                if (row >= M) continue;
                float2 o;
                o.x = acc[mi][ni][half * 2 + 0];
                o.y = acc[mi][ni][half * 2 + 1];
                if (addbias) {
                    o.x += bias[col];
                    o.y += bias[col + 1];
                }
                *(float2*)&C[(size_t)row * Ntot + col] = o;
            }
        }
    }
}

// ---------------- GCN aggregation (fused self-loop+bias+lrelu, fp32 out) ------
template <int F>
__global__ void agg_kernel(const float* __restrict__ xw, const float* __restrict__ bias,
                           float* __restrict__ out, float* __restrict__ combdst, int r) {
    int v = blockIdx.x;
    int t = threadIdx.x;  // 128 threads
    constexpr int J = F / 128;
    float acc[J];
#pragma unroll
    for (int j = 0; j < J; j++) acc[j] = 0.0f;

    const int* rp = &g_rowptr[r * (NN + 1)];
    const int* cs = &g_csr_src[r * EE];
    const float* cc = &g_csr_coef[r * EE];

    int beg = rp[v], end = rp[v + 1];
    for (int e = beg; e < end; e++) {
        int s = cs[e];
        float c = cc[e];
#pragma unroll
        for (int j = 0; j < J; j++)
            acc[j] += c * __ldg(&xw[s * F + t + j * 128]);
    }
    float dv = g_dinv[r * NN + v];
    float dv2 = dv * dv;
#pragma unroll
    for (int j = 0; j < J; j++) {
        size_t idx = (size_t)v * F + t + j * 128;
        float val = acc[j] + xw[idx] * dv2 + bias[t + j * 128];
        val = (val >= 0.0f) ? val : 0.2f * val;
        out[idx] = val;
        if (combdst) combdst[idx] += 0.5f * val;
    }
}

// ---------------- launch ------------------------------------------------------
extern "C" void kernel_launch(void* const* d_in, const int* in_sizes, int n_in,
                              void* d_out, int out_size) {
    const float* x[4] = {(const float*)d_in[0], (const float*)d_in[1],
                         (const float*)d_in[2], (const float*)d_in[3]};
    const void* ed[4] = {d_in[4], d_in[5], d_in[6], d_in[7]};
    const float* W1[4] = {(const float*)d_in[8], (const float*)d_in[10],
                          (const float*)d_in[16], (const float*)d_in[18]};
    const float* B1[4] = {(const float*)d_in[9], (const float*)d_in[11],
                          (const float*)d_in[17], (const float*)d_in[19]};
    const float* W2[4] = {(const float*)d_in[12], (const float*)d_in[14],
                          (const float*)d_in[20], (const float*)d_in[22]};
    const float* B2[4] = {(const float*)d_in[13], (const float*)d_in[15],
                          (const float*)d_in[21], (const float*)d_in[23]};
    float* out = (float*)d_out;

    float *xw1b, *hb, *xw2b;
    __nv_bfloat16 *whi, *wlo;
    cudaGetSymbolAddress((void**)&xw1b, g_xw1);
    cudaGetSymbolAddress((void**)&hb, g_h);
    cudaGetSymbolAddress((void**)&xw2b, g_xw2);
    cudaGetSymbolAddress((void**)&whi, g_Whi);
    cudaGetSymbolAddress((void**)&wlo, g_Wlo);

    cudaFuncSetAttribute(gemm_mma, cudaFuncAttributeMaxDynamicSharedMemorySize, SMB_GEMM);

    // EXACTLY 3 plain streams (leak-free proven config)
    static cudaStream_t s1 = nullptr, s2 = nullptr, s3 = nullptr;
    static cudaEvent_t evRoot = nullptr, evConv = nullptr, evCSR = nullptr;
    static cudaEvent_t evA2_0 = nullptr, evA2_1 = nullptr;
    static cudaEvent_t evE1 = nullptr, evE2 = nullptr, evE3 = nullptr;
    if (!s1) {
        cudaStreamCreateWithFlags(&s1, cudaStreamNonBlocking);
        cudaStreamCreateWithFlags(&s2, cudaStreamNonBlocking);
        cudaStreamCreateWithFlags(&s3, cudaStreamNonBlocking);
        cudaEventCreateWithFlags(&evRoot, cudaEventDisableTiming);
        cudaEventCreateWithFlags(&evConv, cudaEventDisableTiming);
        cudaEventCreateWithFlags(&evCSR, cudaEventDisableTiming);
        cudaEventCreateWithFlags(&evA2_0, cudaEventDisableTiming);
        cudaEventCreateWithFlags(&evA2_1, cudaEventDisableTiming);
        cudaEventCreateWithFlags(&evE1, cudaEventDisableTiming);
        cudaEventCreateWithFlags(&evE2, cudaEventDisableTiming);
        cudaEventCreateWithFlags(&evE3, cudaEventDisableTiming);
    }

    // ---- fork: CSR chain onto s3 ----
    cudaEventRecord(evRoot, 0);
    cudaStreamWaitEvent(s3, evRoot, 0);
    detect_kernel<<<1, 32, 0, s3>>>(ed[0], ed[1], ed[2], ed[3]);
    zero_counts<<<(4 * NN + 255) / 256, 256, 0, s3>>>();
    build_deg<<<dim3((EE + 255) / 256, 4), 256, 0, s3>>>(ed[0], ed[1], ed[2], ed[3]);
    calc_dinv<<<(4 * NN + 255) / 256, 256, 0, s3>>>();
    scan_p1<<<dim3(NCHUNK, 4), CHUNK, 0, s3>>>();
    scan_p2<<<4, 128, 0, s3>>>();
    scan_p3<<<dim3(NCHUNK, 4), CHUNK, 0, s3>>>();
    build_csr<<<dim3((EE + 255) / 256, 4), 256, 0, s3>>>(ed[0], ed[1], ed[2], ed[3]);
    cudaEventRecord(evCSR, s3);

    // ---- weight conversion on stream 0 (the only prep left) ----
    WArgs wa;
    for (int p = 0; p < 4; p++) {
        wa.W[p] = W1[p];     wa.N[p] = 256;     wa.off[p] = WOFF1(p);
        wa.W[4 + p] = W2[p]; wa.N[4 + p] = 128; wa.off[4 + p] = WOFF2(p);
    }
    wa.W[8] = (const float*)d_in[24]; wa.N[8] = 128; wa.off[8] = WOFFR(0);
    wa.W[9] = (const float*)d_in[26]; wa.N[9] = 128; wa.off[9] = WOFFR(1);
    convW10<<<dim3(256, 10), 256>>>(wa, whi, wlo);
    cudaEventRecord(evConv, 0);
    cudaStreamWaitEvent(s1, evConv, 0);
    cudaStreamWaitEvent(s2, evConv, 0);
    cudaStreamWaitEvent(s3, evConv, 0);

    dim3 g1(4, (NN + 127) / 128);   // Ntot=256
    dim3 g2(2, (NN + 127) / 128);   // Ntot=128
    const size_t XSZ = (size_t)NN * 256;
    const size_t X2SZ = (size_t)NN * 128;

    // ---- residual GEMMs early: comb bases (A = raw fp32 inputs) ----
    gemm_mma<<<g2, 256, SMB_GEMM>>>(x[0], whi + WOFFR(0), wlo + WOFFR(0), out, NN, 128,
                                    (const float*)d_in[25], 1);
    gemm_mma<<<g2, 256, SMB_GEMM, s1>>>(x[1], whi + WOFFR(1), wlo + WOFFR(1),
                                        out + (size_t)REGSZ, NN, 128,
                                        (const float*)d_in[27], 1);

    // ---- symmetric per-pipeline chains ----
    cudaStream_t ps[4] = {(cudaStream_t)0, s1, s2, s3};
    for (int p = 0; p < 4; p++) {
        cudaStream_t st = ps[p];
        gemm_mma<<<g1, 256, SMB_GEMM, st>>>(x[p], whi + WOFF1(p), wlo + WOFF1(p),
                                            xw1b + p * XSZ, NN, 256, nullptr, 0);
        if (p != 3) cudaStreamWaitEvent(st, evCSR, 0);  // s3 already ordered after CSR
        agg_kernel<256><<<NN, 128, 0, st>>>(xw1b + p * XSZ, B1[p], hb + p * XSZ, nullptr, p);
        gemm_mma<<<g2, 256, SMB_GEMM, st>>>(hb + p * XSZ, whi + WOFF2(p), wlo + WOFF2(p),
                                            xw2b + p * X2SZ, NN, 128, nullptr, 0);
        // comb serialization: a2(2) after a2(0) [comb_l]; a2(3) after a2(1) [comb_p]
        if (p == 2) cudaStreamWaitEvent(st, evA2_0, 0);
        if (p == 3) cudaStreamWaitEvent(st, evA2_1, 0);
        agg_kernel<128><<<NN, 128, 0, st>>>(xw2b + p * X2SZ, B2[p],
                                            out + (size_t)(2 + p) * REGSZ,
                                            out + (size_t)(p & 1) * REGSZ, p);
        if (p == 0) cudaEventRecord(evA2_0, st);
        if (p == 1) cudaEventRecord(evA2_1, st);
    }

    // ---- join all side streams back to origin ----
    cudaEventRecord(evE1, s1);
    cudaEventRecord(evE2, s2);
    cudaEventRecord(evE3, s3);
    cudaStreamWaitEvent(0, evE1, 0);
    cudaStreamWaitEvent(0, evE2, 0);
    cudaStreamWaitEvent(0, evE3, 0);
}

// round 14
// speedup vs baseline: 1.0315x; 1.0315x over previous
#include <cuda_runtime.h>
#include <cuda_bf16.h>
#include <cuda_fp16.h>
#include <cstdint>

#define NN 50000
#define EE 800000
#define REGSZ (NN * 128)
#define CHUNK 512
#define NCHUNK ((NN + CHUNK - 1) / CHUNK)   // 98

// ---------------- scratch (static device globals; no runtime alloc) ----------
__device__ int   g_deg[4 * NN];
__device__ int   g_cursor[4 * NN];
__device__ int   g_rowptr[4 * (NN + 1)];
__device__ float g_dinv[4 * NN];
__device__ int   g_csr_src[4 * EE];
__device__ float g_csr_coef[4 * EE];
__device__ int   g_is64[4];
__device__ int   g_chunksum[4 * NCHUNK];
__device__ int   g_chunkoff[4 * NCHUNK];
// per-pipeline intermediates: GEMM outputs in fp16 (halves agg gather traffic)
__device__ __half g_xw1[4][NN * 256];
__device__ __half g_xw2[4][NN * 128];
__device__ __nv_bfloat16 g_Hhi[4][NN * 256];
__device__ __nv_bfloat16 g_Hlo[4][NN * 256];
// bf16-split inputs + weights (transposed [n][k])
__device__ __nv_bfloat16 g_Xhi[4][NN * 256];
__device__ __nv_bfloat16 g_Xlo[4][NN * 256];
#define WOFF1(p) ((p) * 65536)
#define WOFF2(p) (262144 + (p) * 32768)
#define WOFFR(i) (393216 + (i) * 32768)
__device__ __nv_bfloat16 g_Whi[458752];
__device__ __nv_bfloat16 g_Wlo[458752];

// ---------------- mma.sync / cp.async helpers --------------------------------
__device__ __forceinline__ uint32_t smem_u32(const void* p) {
    uint32_t a;
    asm("{ .reg .u64 t; cvta.to.shared.u64 t, %1; cvt.u32.u64 %0, t; }" : "=r"(a) : "l"(p));
    return a;
}
__device__ __forceinline__ void ldsm4(uint32_t& r0, uint32_t& r1, uint32_t& r2, uint32_t& r3,
                                      uint32_t a) {
    asm volatile("ldmatrix.sync.aligned.m8n8.x4.shared.b16 {%0,%1,%2,%3}, [%4];"
                 : "=r"(r0), "=r"(r1), "=r"(r2), "=r"(r3) : "r"(a));
}
__device__ __forceinline__ void mma16816(float* d, const uint32_t* a, const uint32_t* b) {
    asm volatile(
        "mma.sync.aligned.m16n8k16.row.col.f32.bf16.bf16.f32 "
        "{%0,%1,%2,%3}, {%4,%5,%6,%7}, {%8,%9}, {%0,%1,%2,%3};"
        : "+f"(d[0]), "+f"(d[1]), "+f"(d[2]), "+f"(d[3])
        : "r"(a[0]), "r"(a[1]), "r"(a[2]), "r"(a[3]), "r"(b[0]), "r"(b[1]));
}
__device__ __forceinline__ void cp16(uint32_t dst, const void* src, bool pred) {
    int sz = pred ? 16 : 0;
    asm volatile("cp.async.ca.shared.global [%0], [%1], 16, %2;"
                 :: "r"(dst), "l"(src), "r"(sz) : "memory");
}
#define CP_COMMIT() asm volatile("cp.async.commit_group;" ::: "memory")

// ---------------- edge dtype sniffing + decode -------------------------------
__global__ void detect_kernel(const void* e0, const void* e1, const void* e2, const void* e3) {
    if (threadIdx.x < 4) {
        const void* p = threadIdx.x == 0 ? e0 : threadIdx.x == 1 ? e1 : threadIdx.x == 2 ? e2 : e3;
        const unsigned int* u = (const unsigned int*)p;
        unsigned int acc = 0;
        for (int i = 0; i < 64; i++) acc |= u[2 * i + 1];
        g_is64[threadIdx.x] = (acc == 0) ? 1 : 0;
    }
}

__device__ __forceinline__ int2 load_edge(const void* ep, int is64, int e) {
    int s, d;
    if (is64) {
        const long long* p = (const long long*)ep;
        s = (int)p[e];
        d = (int)p[EE + e];
    } else {
        const int* p = (const int*)ep;
        s = p[e];
        d = p[EE + e];
    }
    return make_int2(s, d);
}

// ---------------- CSR build ---------------------------------------------------
__global__ void zero_counts() {
    int i = blockIdx.x * blockDim.x + threadIdx.x;
    if (i < 4 * NN) { g_deg[i] = 0; g_cursor[i] = 0; }
}

__global__ void build_deg(const void* e0, const void* e1, const void* e2, const void* e3) {
    int e = blockIdx.x * blockDim.x + threadIdx.x;
    int r = blockIdx.y;
    if (e >= EE) return;
    const void* ep = r == 0 ? e0 : r == 1 ? e1 : r == 2 ? e2 : e3;
    int2 sd = load_edge(ep, g_is64[r], e);
    atomicAdd(&g_deg[r * NN + sd.y], 1);
}

__global__ void calc_dinv() {
    int i = blockIdx.x * blockDim.x + threadIdx.x;
    if (i < 4 * NN) g_dinv[i] = rsqrtf((float)g_deg[i] + 1.0f);
}

__global__ void scan_p1() {
    int r = blockIdx.y;
    int i = blockIdx.x * CHUNK + threadIdx.x;
    int v = (i < NN) ? g_deg[r * NN + i] : 0;
    __shared__ int sh[CHUNK];
    sh[threadIdx.x] = v;
    __syncthreads();
    for (int off = CHUNK / 2; off > 0; off >>= 1) {
        if (threadIdx.x < off) sh[threadIdx.x] += sh[threadIdx.x + off];
        __syncthreads();
    }
    if (threadIdx.x == 0) g_chunksum[r * NCHUNK + blockIdx.x] = sh[0];
}

__global__ void scan_p2() {
    int r = blockIdx.x;
    __shared__ int sh[128];
    int v = (threadIdx.x < NCHUNK) ? g_chunksum[r * NCHUNK + threadIdx.x] : 0;
    sh[threadIdx.x] = v;
    __syncthreads();
    for (int off = 1; off < 128; off <<= 1) {
        int t = (threadIdx.x >= off) ? sh[threadIdx.x - off] : 0;
        __syncthreads();
        sh[threadIdx.x] += t;
        __syncthreads();
    }
    if (threadIdx.x < NCHUNK) g_chunkoff[r * NCHUNK + threadIdx.x] = sh[threadIdx.x] - v;
    if (threadIdx.x == 127) g_rowptr[r * (NN + 1) + NN] = sh[127];
}

__global__ void scan_p3() {
    int r = blockIdx.y;
    int i = blockIdx.x * CHUNK + threadIdx.x;
    int v = (i < NN) ? g_deg[r * NN + i] : 0;
    __shared__ int sh[CHUNK];
    sh[threadIdx.x] = v;
    __syncthreads();
    for (int off = 1; off < CHUNK; off <<= 1) {
        int t = (threadIdx.x >= off) ? sh[threadIdx.x - off] : 0;
        __syncthreads();
        sh[threadIdx.x] += t;
        __syncthreads();
    }
    if (i < NN)
        g_rowptr[r * (NN + 1) + i] = g_chunkoff[r * NCHUNK + blockIdx.x] + sh[threadIdx.x] - v;
}

__global__ void build_csr(const void* e0, const void* e1, const void* e2, const void* e3) {
    int e = blockIdx.x * blockDim.x + threadIdx.x;
    int r = blockIdx.y;
    if (e >= EE) return;
    const void* ep = r == 0 ? e0 : r == 1 ? e1 : r == 2 ? e2 : e3;
    int2 sd = load_edge(ep, g_is64[r], e);
    int pos = g_rowptr[r * (NN + 1) + sd.y] + atomicAdd(&g_cursor[r * NN + sd.y], 1);
    g_csr_src[r * EE + pos] = sd.x;
    g_csr_coef[r * EE + pos] = g_dinv[r * NN + sd.x] * g_dinv[r * NN + sd.y];
}

// ---------------- bf16 split conversions (batched) ----------------------------
__global__ void convA4(const float* __restrict__ x0, const float* __restrict__ x1,
                       const float* __restrict__ x2, const float* __restrict__ x3,
                       __nv_bfloat16* __restrict__ hi, __nv_bfloat16* __restrict__ lo,
                       int n4) {
    int i = blockIdx.x * 256 + threadIdx.x;
    if (i >= n4) return;
    int p = blockIdx.y;
    const float* x = p == 0 ? x0 : p == 1 ? x1 : p == 2 ? x2 : x3;
    size_t off = (size_t)p * NN * 256;
    float4 v = ((const float4*)x)[i];
    __nv_bfloat16 h0 = __float2bfloat16(v.x);
    __nv_bfloat16 h1 = __float2bfloat16(v.y);
    __nv_bfloat16 h2 = __float2bfloat16(v.z);
    __nv_bfloat16 h3 = __float2bfloat16(v.w);
    __nv_bfloat162* hp = (__nv_bfloat162*)&hi[off + (size_t)i * 4];
    hp[0] = __nv_bfloat162(h0, h1);
    hp[1] = __nv_bfloat162(h2, h3);
    __nv_bfloat162* lp = (__nv_bfloat162*)&lo[off + (size_t)i * 4];
    lp[0] = __nv_bfloat162(__float2bfloat16(v.x - __bfloat162float(h0)),
                           __float2bfloat16(v.y - __bfloat162float(h1)));
    lp[1] = __nv_bfloat162(__float2bfloat16(v.z - __bfloat162float(h2)),
                           __float2bfloat16(v.w - __bfloat162float(h3)));
}

struct WArgs {
    const float* W[10];
    int N[10];
    int off[10];
};
__global__ void convW10(WArgs a, __nv_bfloat16* __restrict__ hi, __nv_bfloat16* __restrict__ lo) {
    int m = blockIdx.y;
    int i = blockIdx.x * 256 + threadIdx.x;
    int N = a.N[m];
    if (i >= N * 256) return;
    int n = i >> 8, k = i & 255;
    float v = a.W[m][k * N + n];
    __nv_bfloat16 h = __float2bfloat16(v);
    hi[a.off[m] + i] = h;
    lo[a.off[m] + i] = __float2bfloat16(v - __bfloat162float(h));
}

// ---------------- mma.sync GEMM, 3-stage cp.async K32 pipeline ---------------
// Output: Ch!=nullptr -> fp16 C; else fp32 C, optional comb epilogue.
#define KC 32
#define LDA 40
#define S_AHI 0
#define S_ALO (128 * LDA)
#define S_BHI (2 * 128 * LDA)
#define S_BLO (2 * 128 * LDA + 64 * LDA)
#define STG_E (2 * 128 * LDA + 2 * 64 * LDA)   // 15360 elems = 30720 B/stage
#define NSTG 3
#define SMB_GEMM (NSTG * STG_E * 2)            // 92160 B

__global__ void __launch_bounds__(256, 2) gemm_mma(
    const __nv_bfloat16* __restrict__ Ahi, const __nv_bfloat16* __restrict__ Alo,
    const __nv_bfloat16* __restrict__ Bhi, const __nv_bfloat16* __restrict__ Blo,
    float* __restrict__ C, __half* __restrict__ Ch, int M, int Ntot,
    const float* __restrict__ bias, const float* __restrict__ P,
    const float* __restrict__ Q, int comb) {
    extern __shared__ __nv_bfloat16 sm[];
    uint32_t sb = smem_u32(sm);
    int tid = threadIdx.x, lane = tid & 31, w = tid >> 5;
    int wm = w & 3, wn = w >> 2;
    int m0 = blockIdx.y * 128, n0 = blockIdx.x * 64;

    float acc[2][4][4];
#pragma unroll
    for (int mi = 0; mi < 2; mi++)
#pragma unroll
        for (int ni = 0; ni < 4; ni++)
#pragma unroll
            for (int q = 0; q < 4; q++) acc[mi][ni][q] = 0.0f;

    int st_row = tid >> 2;
    int st_col = (tid & 3) * 8;

    uint32_t a_off[2], b_off[2];
#pragma unroll
    for (int mi = 0; mi < 2; mi++)
        a_off[mi] = (uint32_t)((wm * 32 + mi * 16 + (lane & 15)) * LDA + (lane >> 4) * 8);
#pragma unroll
    for (int bt = 0; bt < 2; bt++)
        b_off[bt] = (uint32_t)((wn * 32 + bt * 16 + ((lane >> 4) << 3) + (lane & 7)) * LDA +
                               ((lane >> 3) & 1) * 8);

    auto issue = [&](int c) {
        int k0 = c * KC;
        uint32_t base = sb + (uint32_t)((c % NSTG) * STG_E * 2);
#pragma unroll
        for (int i = 0; i < 2; i++) {
            int row = st_row + i * 64;
            int gr = m0 + row;
            bool ok = gr < M;
            int grc = ok ? gr : (M - 1);
            cp16(base + (uint32_t)((S_AHI + row * LDA + st_col) * 2),
                 &Ahi[(size_t)grc * 256 + k0 + st_col], ok);
            cp16(base + (uint32_t)((S_ALO + row * LDA + st_col) * 2),
                 &Alo[(size_t)grc * 256 + k0 + st_col], ok);
        }
        cp16(base + (uint32_t)((S_BHI + st_row * LDA + st_col) * 2),
             &Bhi[(size_t)(n0 + st_row) * 256 + k0 + st_col], true);
        cp16(base + (uint32_t)((S_BLO + st_row * LDA + st_col) * 2),
             &Blo[(size_t)(n0 + st_row) * 256 + k0 + st_col], true);
        CP_COMMIT();
    };

    issue(0);
    issue(1);

#pragma unroll
    for (int c = 0; c < 8; c++) {
        if (c < 7) asm volatile("cp.async.wait_group 1;" ::: "memory");
        else       asm volatile("cp.async.wait_group 0;" ::: "memory");
        __syncthreads();
        if (c + 2 < 8) issue(c + 2);

        uint32_t base = sb + (uint32_t)((c % NSTG) * STG_E * 2);
#pragma unroll
        for (int ks = 0; ks < 2; ks++) {
            int k = ks * 16;
            uint32_t aH[2][4], aL[2][4], bH[4][2], bL[4][2];
#pragma unroll
            for (int mi = 0; mi < 2; mi++) {
                ldsm4(aH[mi][0], aH[mi][1], aH[mi][2], aH[mi][3],
                      base + ((S_AHI + a_off[mi] + k) << 1));
                ldsm4(aL[mi][0], aL[mi][1], aL[mi][2], aL[mi][3],
                      base + ((S_ALO + a_off[mi] + k) << 1));
            }
#pragma unroll
            for (int bt = 0; bt < 2; bt++) {
                uint32_t r0, r1, r2, r3;
                ldsm4(r0, r1, r2, r3, base + ((S_BHI + b_off[bt] + k) << 1));
                bH[bt * 2][0] = r0; bH[bt * 2][1] = r1;
                bH[bt * 2 + 1][0] = r2; bH[bt * 2 + 1][1] = r3;
                ldsm4(r0, r1, r2, r3, base + ((S_BLO + b_off[bt] + k) << 1));
                bL[bt * 2][0] = r0; bL[bt * 2][1] = r1;
                bL[bt * 2 + 1][0] = r2; bL[bt * 2 + 1][1] = r3;
            }
#pragma unroll
            for (int mi = 0; mi < 2; mi++)
#pragma unroll
                for (int ni = 0; ni < 4; ni++) {
                    mma16816(acc[mi][ni], aH[mi], bH[ni]);
                    mma16816(acc[mi][ni], aH[mi], bL[ni]);
                    mma16816(acc[mi][ni], aL[mi], bH[ni]);
                }
        }
    }

#pragma unroll
    for (int mi = 0; mi < 2; mi++) {
#pragma unroll
        for (int ni = 0; ni < 4; ni++) {
            int col = n0 + wn * 32 + ni * 8 + (lane & 3) * 2;
            int r_lo = m0 + wm * 32 + mi * 16 + (lane >> 2);
            int r_hi = r_lo + 8;
#pragma unroll
            for (int half = 0; half < 2; half++) {
                int row = half ? r_hi : r_lo;
                if (row >= M) continue;
                float2 o;
                o.x = acc[mi][ni][half * 2 + 0];
                o.y = acc[mi][ni][half * 2 + 1];
                size_t base = (size_t)row * Ntot + col;
                if (Ch) {
                    *(__half2*)&Ch[base] = __floats2half2_rn(o.x, o.y);
                } else {
                    if (comb) {
                        o.x += bias[col] + 0.5f * (P[base] + Q[base]);
                        o.y += bias[col + 1] + 0.5f * (P[base + 1] + Q[base + 1]);
                    }
                    *(float2*)&C[base] = o;
                }
            }
        }
    }
}

// ---------------- GCN aggregation (fp16 gather; fused self+bias+lrelu) --------
// EMIT16: write bf16 hi/lo split (layer-1); else fp32 out (layer-2)
template <int F, bool EMIT16>
__global__ void agg_kernel(const __half* __restrict__ xw, const float* __restrict__ bias,
                           float* __restrict__ out, __nv_bfloat16* __restrict__ ohi,
                           __nv_bfloat16* __restrict__ olo, int r) {
    int v = blockIdx.x;
    int t = threadIdx.x;  // 128 threads
    constexpr int J = F / 128;
    float acc[J];
#pragma unroll
    for (int j = 0; j < J; j++) acc[j] = 0.0f;

    const int* rp = &g_rowptr[r * (NN + 1)];
    const int* cs = &g_csr_src[r * EE];
    const float* cc = &g_csr_coef[r * EE];

    int beg = rp[v], end = rp[v + 1];
    for (int e = beg; e < end; e++) {
        int s = cs[e];
        float c = cc[e];
#pragma unroll
        for (int j = 0; j < J; j++)
            acc[j] += c * __half2float(__ldg(&xw[(size_t)s * F + t + j * 128]));
    }
    float dv = g_dinv[r * NN + v];
    float dv2 = dv * dv;
#pragma unroll
    for (int j = 0; j < J; j++) {
        size_t idx = (size_t)v * F + t + j * 128;
        float val = acc[j] + __half2float(xw[idx]) * dv2 + bias[t + j * 128];
        val = (val >= 0.0f) ? val : 0.2f * val;
        if (EMIT16) {
            __nv_bfloat16 h = __float2bfloat16(val);
            ohi[idx] = h;
            olo[idx] = __float2bfloat16(val - __bfloat162float(h));
        } else {
            out[idx] = val;
        }
    }
}

// ---------------- launch ------------------------------------------------------
extern "C" void kernel_launch(void* const* d_in, const int* in_sizes, int n_in,
                              void* d_out, int out_size) {
    const float* x[4] = {(const float*)d_in[0], (const float*)d_in[1],
                         (const float*)d_in[2], (const float*)d_in[3]};
    const void* ed[4] = {d_in[4], d_in[5], d_in[6], d_in[7]};
    const float* W1[4] = {(const float*)d_in[8], (const float*)d_in[10],
                          (const float*)d_in[16], (const float*)d_in[18]};
    const float* B1[4] = {(const float*)d_in[9], (const float*)d_in[11],
                          (const float*)d_in[17], (const float*)d_in[19]};
    const float* W2[4] = {(const float*)d_in[12], (const float*)d_in[14],
                          (const float*)d_in[20], (const float*)d_in[22]};
    const float* B2[4] = {(const float*)d_in[13], (const float*)d_in[15],
                          (const float*)d_in[21], (const float*)d_in[23]};
    float* out = (float*)d_out;

    __half *xw1b, *xw2b;
    __nv_bfloat16 *xhi, *xlo, *hhib, *hlob, *whi, *wlo;
    cudaGetSymbolAddress((void**)&xw1b, g_xw1);
    cudaGetSymbolAddress((void**)&xw2b, g_xw2);
    cudaGetSymbolAddress((void**)&xhi, g_Xhi);
    cudaGetSymbolAddress((void**)&xlo, g_Xlo);
    cudaGetSymbolAddress((void**)&hhib, g_Hhi);
    cudaGetSymbolAddress((void**)&hlob, g_Hlo);
    cudaGetSymbolAddress((void**)&whi, g_Whi);
    cudaGetSymbolAddress((void**)&wlo, g_Wlo);

    cudaFuncSetAttribute(gemm_mma, cudaFuncAttributeMaxDynamicSharedMemorySize, SMB_GEMM);

    // EXACTLY 3 plain streams (leak-free proven config)
    static cudaStream_t s1 = nullptr, s2 = nullptr, s3 = nullptr;
    static cudaEvent_t evRoot = nullptr, evConv = nullptr, evCSR = nullptr;
    static cudaEvent_t evS2 = nullptr, evS3 = nullptr, evS1J = nullptr;
    if (!s1) {
        cudaStreamCreateWithFlags(&s1, cudaStreamNonBlocking);
        cudaStreamCreateWithFlags(&s2, cudaStreamNonBlocking);
        cudaStreamCreateWithFlags(&s3, cudaStreamNonBlocking);
        cudaEventCreateWithFlags(&evRoot, cudaEventDisableTiming);
        cudaEventCreateWithFlags(&evConv, cudaEventDisableTiming);
        cudaEventCreateWithFlags(&evCSR, cudaEventDisableTiming);
        cudaEventCreateWithFlags(&evS2, cudaEventDisableTiming);
        cudaEventCreateWithFlags(&evS3, cudaEventDisableTiming);
        cudaEventCreateWithFlags(&evS1J, cudaEventDisableTiming);
    }

    // ---- fork: CSR chain onto s3 ----
    cudaEventRecord(evRoot, 0);
    cudaStreamWaitEvent(s3, evRoot, 0);
    detect_kernel<<<1, 32, 0, s3>>>(ed[0], ed[1], ed[2], ed[3]);
    zero_counts<<<(4 * NN + 255) / 256, 256, 0, s3>>>();
    build_deg<<<dim3((EE + 255) / 256, 4), 256, 0, s3>>>(ed[0], ed[1], ed[2], ed[3]);
    calc_dinv<<<(4 * NN + 255) / 256, 256, 0, s3>>>();
    scan_p1<<<dim3(NCHUNK, 4), CHUNK, 0, s3>>>();
    scan_p2<<<4, 128, 0, s3>>>();
    scan_p3<<<dim3(NCHUNK, 4), CHUNK, 0, s3>>>();
    build_csr<<<dim3((EE + 255) / 256, 4), 256, 0, s3>>>(ed[0], ed[1], ed[2], ed[3]);
    cudaEventRecord(evCSR, s3);

    // ---- conversions on stream 0 ----
    WArgs wa;
    for (int p = 0; p < 4; p++) {
        wa.W[p] = W1[p];     wa.N[p] = 256;     wa.off[p] = WOFF1(p);
        wa.W[4 + p] = W2[p]; wa.N[4 + p] = 128; wa.off[4 + p] = WOFF2(p);
    }
    wa.W[8] = (const float*)d_in[24]; wa.N[8] = 128; wa.off[8] = WOFFR(0);
    wa.W[9] = (const float*)d_in[26]; wa.N[9] = 128; wa.off[9] = WOFFR(1);
    convW10<<<dim3(256, 10), 256>>>(wa, whi, wlo);
    const int n4 = NN * 256 / 4;
    convA4<<<dim3((n4 + 255) / 256, 4), 256>>>(x[0], x[1], x[2], x[3], xhi, xlo, n4);
    cudaEventRecord(evConv, 0);
    cudaStreamWaitEvent(s1, evConv, 0);
    cudaStreamWaitEvent(s2, evConv, 0);
    cudaStreamWaitEvent(s3, evConv, 0);

    dim3 g1(4, (NN + 127) / 128);   // Ntot=256
    dim3 g2(2, (NN + 127) / 128);   // Ntot=128
    const size_t XSZ = (size_t)NN * 256;
    const size_t X2SZ = (size_t)NN * 128;

    cudaStream_t ps[4] = {(cudaStream_t)0, s1, s2, s3};
    for (int p = 0; p < 4; p++) {
        cudaStream_t st = ps[p];
        gemm_mma<<<g1, 256, SMB_GEMM, st>>>(xhi + p * XSZ, xlo + p * XSZ, whi + WOFF1(p),
                                            wlo + WOFF1(p), nullptr, xw1b + p * XSZ,
                                            NN, 256, nullptr, nullptr, nullptr, 0);
        if (p != 3) cudaStreamWaitEvent(st, evCSR, 0);  // s3 already ordered after CSR
        agg_kernel<256, true><<<NN, 128, 0, st>>>(xw1b + p * XSZ, B1[p], nullptr,
                                                  hhib + p * XSZ, hlob + p * XSZ, p);
        gemm_mma<<<g2, 256, SMB_GEMM, st>>>(hhib + p * XSZ, hlob + p * XSZ, whi + WOFF2(p),
                                            wlo + WOFF2(p), nullptr, xw2b + p * X2SZ,
                                            NN, 128, nullptr, nullptr, nullptr, 0);
        agg_kernel<128, false><<<NN, 128, 0, st>>>(xw2b + p * X2SZ, B2[p],
                                                   out + (size_t)(2 + p) * REGSZ,
                                                   nullptr, nullptr, p);
    }

    // ---- join + residual/combine GEMMs (R8 structure) ----
    cudaEventRecord(evS2, s2);
    cudaStreamWaitEvent(0, evS2, 0);
    gemm_mma<<<g2, 256, SMB_GEMM>>>(xhi, xlo, whi + WOFFR(0), wlo + WOFFR(0), out, nullptr,
                                    NN, 128, (const float*)d_in[25], out + (size_t)2 * REGSZ,
                                    out + (size_t)4 * REGSZ, 1);
    cudaEventRecord(evS3, s3);
    cudaStreamWaitEvent(s1, evS3, 0);
    gemm_mma<<<g2, 256, SMB_GEMM, s1>>>(xhi + XSZ, xlo + XSZ, whi + WOFFR(1), wlo + WOFFR(1),
                                        out + (size_t)REGSZ, nullptr, NN, 128,
                                        (const float*)d_in[27], out + (size_t)3 * REGSZ,
                                        out + (size_t)5 * REGSZ, 1);
    cudaEventRecord(evS1J, s1);
    cudaStreamWaitEvent(0, evS1J, 0);
}

// round 15
// speedup vs baseline: 1.0906x; 1.0573x over previous
#include <cuda_runtime.h>
#include <cuda_bf16.h>
#include <cuda_fp16.h>
#include <cstdint>

#define NN 50000
#define EE 800000
#define REGSZ (NN * 128)
#define CHUNK 512
#define NCHUNK ((NN + CHUNK - 1) / CHUNK)   // 98

// ---------------- scratch (static device globals; no runtime alloc) ----------
__device__ int   g_deg[4 * NN];
__device__ int   g_cursor[4 * NN];
__device__ int   g_rowptr[4 * (NN + 1)];
__device__ float g_dinv[4 * NN];
__device__ int2  g_csr_pk[4 * EE];          // packed {src, coef-as-int}
__device__ int   g_is64[4];
__device__ int   g_chunksum[4 * NCHUNK];
__device__ int   g_chunkoff[4 * NCHUNK];
// per-pipeline intermediates: GEMM outputs in fp16
__device__ __half g_xw1[4][NN * 256];
__device__ __half g_xw2[4][NN * 128];
__device__ __nv_bfloat16 g_Hhi[4][NN * 256];
__device__ __nv_bfloat16 g_Hlo[4][NN * 256];
// bf16-split inputs + weights (transposed [n][k])
__device__ __nv_bfloat16 g_Xhi[4][NN * 256];
__device__ __nv_bfloat16 g_Xlo[4][NN * 256];
#define WOFF1(p) ((p) * 65536)
#define WOFF2(p) (262144 + (p) * 32768)
#define WOFFR(i) (393216 + (i) * 32768)
__device__ __nv_bfloat16 g_Whi[458752];
__device__ __nv_bfloat16 g_Wlo[458752];

// ---------------- mma.sync / cp.async helpers --------------------------------
__device__ __forceinline__ uint32_t smem_u32(const void* p) {
    uint32_t a;
    asm("{ .reg .u64 t; cvta.to.shared.u64 t, %1; cvt.u32.u64 %0, t; }" : "=r"(a) : "l"(p));
    return a;
}
__device__ __forceinline__ void ldsm4(uint32_t& r0, uint32_t& r1, uint32_t& r2, uint32_t& r3,
                                      uint32_t a) {
    asm volatile("ldmatrix.sync.aligned.m8n8.x4.shared.b16 {%0,%1,%2,%3}, [%4];"
                 : "=r"(r0), "=r"(r1), "=r"(r2), "=r"(r3) : "r"(a));
}
__device__ __forceinline__ void mma16816(float* d, const uint32_t* a, const uint32_t* b) {
    asm volatile(
        "mma.sync.aligned.m16n8k16.row.col.f32.bf16.bf16.f32 "
        "{%0,%1,%2,%3}, {%4,%5,%6,%7}, {%8,%9}, {%0,%1,%2,%3};"
        : "+f"(d[0]), "+f"(d[1]), "+f"(d[2]), "+f"(d[3])
        : "r"(a[0]), "r"(a[1]), "r"(a[2]), "r"(a[3]), "r"(b[0]), "r"(b[1]));
}
__device__ __forceinline__ void cp16(uint32_t dst, const void* src, bool pred) {
    int sz = pred ? 16 : 0;
    asm volatile("cp.async.ca.shared.global [%0], [%1], 16, %2;"
                 :: "r"(dst), "l"(src), "r"(sz) : "memory");
}
#define CP_COMMIT() asm volatile("cp.async.commit_group;" ::: "memory")

// ---------------- edge dtype sniffing + decode -------------------------------
__global__ void detect_kernel(const void* e0, const void* e1, const void* e2, const void* e3) {
    if (threadIdx.x < 4) {
        const void* p = threadIdx.x == 0 ? e0 : threadIdx.x == 1 ? e1 : threadIdx.x == 2 ? e2 : e3;
        const unsigned int* u = (const unsigned int*)p;
        unsigned int acc = 0;
        for (int i = 0; i < 64; i++) acc |= u[2 * i + 1];
        g_is64[threadIdx.x] = (acc == 0) ? 1 : 0;
    }
}

__device__ __forceinline__ int2 load_edge(const void* ep, int is64, int e) {
    int s, d;
    if (is64) {
        const long long* p = (const long long*)ep;
        s = (int)p[e];
        d = (int)p[EE + e];
    } else {
        const int* p = (const int*)ep;
        s = p[e];
        d = p[EE + e];
    }
    return make_int2(s, d);
}

// ---------------- CSR build ---------------------------------------------------
__global__ void zero_counts() {
    int i = blockIdx.x * blockDim.x + threadIdx.x;
    if (i < 4 * NN) { g_deg[i] = 0; g_cursor[i] = 0; }
}

__global__ void build_deg(const void* e0, const void* e1, const void* e2, const void* e3) {
    int e = blockIdx.x * blockDim.x + threadIdx.x;
    int r = blockIdx.y;
    if (e >= EE) return;
    const void* ep = r == 0 ? e0 : r == 1 ? e1 : r == 2 ? e2 : e3;
    int2 sd = load_edge(ep, g_is64[r], e);
    atomicAdd(&g_deg[r * NN + sd.y], 1);
}

__global__ void calc_dinv() {
    int i = blockIdx.x * blockDim.x + threadIdx.x;
    if (i < 4 * NN) g_dinv[i] = rsqrtf((float)g_deg[i] + 1.0f);
}

__global__ void scan_p1() {
    int r = blockIdx.y;
    int i = blockIdx.x * CHUNK + threadIdx.x;
    int v = (i < NN) ? g_deg[r * NN + i] : 0;
    __shared__ int sh[CHUNK];
    sh[threadIdx.x] = v;
    __syncthreads();
    for (int off = CHUNK / 2; off > 0; off >>= 1) {
        if (threadIdx.x < off) sh[threadIdx.x] += sh[threadIdx.x + off];
        __syncthreads();
    }
    if (threadIdx.x == 0) g_chunksum[r * NCHUNK + blockIdx.x] = sh[0];
}

__global__ void scan_p2() {
    int r = blockIdx.x;
    __shared__ int sh[128];
    int v = (threadIdx.x < NCHUNK) ? g_chunksum[r * NCHUNK + threadIdx.x] : 0;
    sh[threadIdx.x] = v;
    __syncthreads();
    for (int off = 1; off < 128; off <<= 1) {
        int t = (threadIdx.x >= off) ? sh[threadIdx.x - off] : 0;
        __syncthreads();
        sh[threadIdx.x] += t;
        __syncthreads();
    }
    if (threadIdx.x < NCHUNK) g_chunkoff[r * NCHUNK + threadIdx.x] = sh[threadIdx.x] - v;
    if (threadIdx.x == 127) g_rowptr[r * (NN + 1) + NN] = sh[127];
}

__global__ void scan_p3() {
    int r = blockIdx.y;
    int i = blockIdx.x * CHUNK + threadIdx.x;
    int v = (i < NN) ? g_deg[r * NN + i] : 0;
    __shared__ int sh[CHUNK];
    sh[threadIdx.x] = v;
    __syncthreads();
    for (int off = 1; off < CHUNK; off <<= 1) {
        int t = (threadIdx.x >= off) ? sh[threadIdx.x - off] : 0;
        __syncthreads();
        sh[threadIdx.x] += t;
        __syncthreads();
    }
    if (i < NN)
        g_rowptr[r * (NN + 1) + i] = g_chunkoff[r * NCHUNK + blockIdx.x] + sh[threadIdx.x] - v;
}

__global__ void build_csr(const void* e0, const void* e1, const void* e2, const void* e3) {
    int e = blockIdx.x * blockDim.x + threadIdx.x;
    int r = blockIdx.y;
    if (e >= EE) return;
    const void* ep = r == 0 ? e0 : r == 1 ? e1 : r == 2 ? e2 : e3;
    int2 sd = load_edge(ep, g_is64[r], e);
    int pos = g_rowptr[r * (NN + 1) + sd.y] + atomicAdd(&g_cursor[r * NN + sd.y], 1);
    float coef = g_dinv[r * NN + sd.x] * g_dinv[r * NN + sd.y];
    g_csr_pk[r * EE + pos] = make_int2(sd.x, __float_as_int(coef));
}

// ---------------- bf16 split conversions (batched) ----------------------------
__global__ void convA4(const float* __restrict__ x0, const float* __restrict__ x1,
                       const float* __restrict__ x2, const float* __restrict__ x3,
                       __nv_bfloat16* __restrict__ hi, __nv_bfloat16* __restrict__ lo,
                       int n4) {
    int i = blockIdx.x * 256 + threadIdx.x;
    if (i >= n4) return;
    int p = blockIdx.y;
    const float* x = p == 0 ? x0 : p == 1 ? x1 : p == 2 ? x2 : x3;
    size_t off = (size_t)p * NN * 256;
    float4 v = ((const float4*)x)[i];
    __nv_bfloat16 h0 = __float2bfloat16(v.x);
    __nv_bfloat16 h1 = __float2bfloat16(v.y);
    __nv_bfloat16 h2 = __float2bfloat16(v.z);
    __nv_bfloat16 h3 = __float2bfloat16(v.w);
    __nv_bfloat162* hp = (__nv_bfloat162*)&hi[off + (size_t)i * 4];
    hp[0] = __nv_bfloat162(h0, h1);
    hp[1] = __nv_bfloat162(h2, h3);
    __nv_bfloat162* lp = (__nv_bfloat162*)&lo[off + (size_t)i * 4];
    lp[0] = __nv_bfloat162(__float2bfloat16(v.x - __bfloat162float(h0)),
                           __float2bfloat16(v.y - __bfloat162float(h1)));
    lp[1] = __nv_bfloat162(__float2bfloat16(v.z - __bfloat162float(h2)),
                           __float2bfloat16(v.w - __bfloat162float(h3)));
}

struct WArgs {
    const float* W[10];
    int N[10];
    int off[10];
};
__global__ void convW10(WArgs a, __nv_bfloat16* __restrict__ hi, __nv_bfloat16* __restrict__ lo) {
    int m = blockIdx.y;
    int i = blockIdx.x * 256 + threadIdx.x;
    int N = a.N[m];
    if (i >= N * 256) return;
    int n = i >> 8, k = i & 255;
    float v = a.W[m][k * N + n];
    __nv_bfloat16 h = __float2bfloat16(v);
    hi[a.off[m] + i] = h;
    lo[a.off[m] + i] = __float2bfloat16(v - __bfloat162float(h));
}

// ---------------- mma.sync GEMM, 3-stage cp.async K32 pipeline ---------------
#define KC 32
#define LDA 40
#define S_AHI 0
#define S_ALO (128 * LDA)
#define S_BHI (2 * 128 * LDA)
#define S_BLO (2 * 128 * LDA + 64 * LDA)
#define STG_E (2 * 128 * LDA + 2 * 64 * LDA)   // 15360 elems = 30720 B/stage
#define NSTG 3
#define SMB_GEMM (NSTG * STG_E * 2)            // 92160 B

__global__ void __launch_bounds__(256, 2) gemm_mma(
    const __nv_bfloat16* __restrict__ Ahi, const __nv_bfloat16* __restrict__ Alo,
    const __nv_bfloat16* __restrict__ Bhi, const __nv_bfloat16* __restrict__ Blo,
    float* __restrict__ C, __half* __restrict__ Ch, int M, int Ntot,
    const float* __restrict__ bias, const float* __restrict__ P,
    const float* __restrict__ Q, int comb) {
    extern __shared__ __nv_bfloat16 sm[];
    uint32_t sb = smem_u32(sm);
    int tid = threadIdx.x, lane = tid & 31, w = tid >> 5;
    int wm = w & 3, wn = w >> 2;
    int m0 = blockIdx.y * 128, n0 = blockIdx.x * 64;

    float acc[2][4][4];
#pragma unroll
    for (int mi = 0; mi < 2; mi++)
#pragma unroll
        for (int ni = 0; ni < 4; ni++)
#pragma unroll
            for (int q = 0; q < 4; q++) acc[mi][ni][q] = 0.0f;

    int st_row = tid >> 2;
    int st_col = (tid & 3) * 8;

    uint32_t a_off[2], b_off[2];
#pragma unroll
    for (int mi = 0; mi < 2; mi++)
        a_off[mi] = (uint32_t)((wm * 32 + mi * 16 + (lane & 15)) * LDA + (lane >> 4) * 8);
#pragma unroll
    for (int bt = 0; bt < 2; bt++)
        b_off[bt] = (uint32_t)((wn * 32 + bt * 16 + ((lane >> 4) << 3) + (lane & 7)) * LDA +
                               ((lane >> 3) & 1) * 8);

    auto issue = [&](int c) {
        int k0 = c * KC;
        uint32_t base = sb + (uint32_t)((c % NSTG) * STG_E * 2);
#pragma unroll
        for (int i = 0; i < 2; i++) {
            int row = st_row + i * 64;
            int gr = m0 + row;
            bool ok = gr < M;
            int grc = ok ? gr : (M - 1);
            cp16(base + (uint32_t)((S_AHI + row * LDA + st_col) * 2),
                 &Ahi[(size_t)grc * 256 + k0 + st_col], ok);
            cp16(base + (uint32_t)((S_ALO + row * LDA + st_col) * 2),
                 &Alo[(size_t)grc * 256 + k0 + st_col], ok);
        }
        cp16(base + (uint32_t)((S_BHI + st_row * LDA + st_col) * 2),
             &Bhi[(size_t)(n0 + st_row) * 256 + k0 + st_col], true);
        cp16(base + (uint32_t)((S_BLO + st_row * LDA + st_col) * 2),
             &Blo[(size_t)(n0 + st_row) * 256 + k0 + st_col], true);
        CP_COMMIT();
    };

    issue(0);
    issue(1);

#pragma unroll
    for (int c = 0; c < 8; c++) {
        if (c < 7) asm volatile("cp.async.wait_group 1;" ::: "memory");
        else       asm volatile("cp.async.wait_group 0;" ::: "memory");
        __syncthreads();
        if (c + 2 < 8) issue(c + 2);

        uint32_t base = sb + (uint32_t)((c % NSTG) * STG_E * 2);
#pragma unroll
        for (int ks = 0; ks < 2; ks++) {
            int k = ks * 16;
            uint32_t aH[2][4], aL[2][4], bH[4][2], bL[4][2];
#pragma unroll
            for (int mi = 0; mi < 2; mi++) {
                ldsm4(aH[mi][0], aH[mi][1], aH[mi][2], aH[mi][3],
                      base + ((S_AHI + a_off[mi] + k) << 1));
                ldsm4(aL[mi][0], aL[mi][1], aL[mi][2], aL[mi][3],
                      base + ((S_ALO + a_off[mi] + k) << 1));
            }
#pragma unroll
            for (int bt = 0; bt < 2; bt++) {
                uint32_t r0, r1, r2, r3;
                ldsm4(r0, r1, r2, r3, base + ((S_BHI + b_off[bt] + k) << 1));
                bH[bt * 2][0] = r0; bH[bt * 2][1] = r1;
                bH[bt * 2 + 1][0] = r2; bH[bt * 2 + 1][1] = r3;
                ldsm4(r0, r1, r2, r3, base + ((S_BLO + b_off[bt] + k) << 1));
                bL[bt * 2][0] = r0; bL[bt * 2][1] = r1;
                bL[bt * 2 + 1][0] = r2; bL[bt * 2 + 1][1] = r3;
            }
#pragma unroll
            for (int mi = 0; mi < 2; mi++)
#pragma unroll
                for (int ni = 0; ni < 4; ni++) {
                    mma16816(acc[mi][ni], aH[mi], bH[ni]);
                    mma16816(acc[mi][ni], aH[mi], bL[ni]);
                    mma16816(acc[mi][ni], aL[mi], bH[ni]);
                }
        }
    }

#pragma unroll
    for (int mi = 0; mi < 2; mi++) {
#pragma unroll
        for (int ni = 0; ni < 4; ni++) {
            int col = n0 + wn * 32 + ni * 8 + (lane & 3) * 2;
            int r_lo = m0 + wm * 32 + mi * 16 + (lane >> 2);
            int r_hi = r_lo + 8;
#pragma unroll
            for (int half = 0; half < 2; half++) {
                int row = half ? r_hi : r_lo;
                if (row >= M) continue;
                float2 o;
                o.x = acc[mi][ni][half * 2 + 0];
                o.y = acc[mi][ni][half * 2 + 1];
                size_t base = (size_t)row * Ntot + col;
                if (Ch) {
                    *(__half2*)&Ch[base] = __floats2half2_rn(o.x, o.y);
                } else {
                    if (comb) {
                        o.x += bias[col] + 0.5f * (P[base] + Q[base]);
                        o.y += bias[col + 1] + 0.5f * (P[base + 1] + Q[base + 1]);
                    }
                    *(float2*)&C[base] = o;
                }
            }
        }
    }
}

// ---------------- agg layer-1: F=256, 128 thr/node, half2 gathers, unroll-4 ---
__global__ void agg1_kernel(const __half* __restrict__ xw, const float* __restrict__ bias,
                            __nv_bfloat16* __restrict__ ohi, __nv_bfloat16* __restrict__ olo,
                            int r) {
    int v = blockIdx.x;
    int t = threadIdx.x;  // half2 lane: features 2t, 2t+1
    const int2* pk = &g_csr_pk[r * EE];
    const __half2* xw2 = (const __half2*)xw;  // rows of 128 half2

    int beg = g_rowptr[r * (NN + 1) + v], end = g_rowptr[r * (NN + 1) + v + 1];
    float ax = 0.f, ay = 0.f;
    int e = beg;
    for (; e + 4 <= end; e += 4) {
        int2 p0 = __ldg(&pk[e]), p1 = __ldg(&pk[e + 1]);
        int2 p2 = __ldg(&pk[e + 2]), p3 = __ldg(&pk[e + 3]);
        __half2 g0 = __ldg(&xw2[(size_t)p0.x * 128 + t]);
        __half2 g1 = __ldg(&xw2[(size_t)p1.x * 128 + t]);
        __half2 g2 = __ldg(&xw2[(size_t)p2.x * 128 + t]);
        __half2 g3 = __ldg(&xw2[(size_t)p3.x * 128 + t]);
        float c0 = __int_as_float(p0.y), c1 = __int_as_float(p1.y);
        float c2 = __int_as_float(p2.y), c3 = __int_as_float(p3.y);
        float2 f0 = __half22float2(g0), f1 = __half22float2(g1);
        float2 f2 = __half22float2(g2), f3 = __half22float2(g3);
        ax += c0 * f0.x + c1 * f1.x + c2 * f2.x + c3 * f3.x;
        ay += c0 * f0.y + c1 * f1.y + c2 * f2.y + c3 * f3.y;
    }
    for (; e < end; e++) {
        int2 p = __ldg(&pk[e]);
        float c = __int_as_float(p.y);
        float2 f = __half22float2(__ldg(&xw2[(size_t)p.x * 128 + t]));
        ax += c * f.x;
        ay += c * f.y;
    }
    float dv = g_dinv[r * NN + v];
    float dv2 = dv * dv;
    float2 self = __half22float2(xw2[(size_t)v * 128 + t]);
    float2 b2 = *(const float2*)&bias[2 * t];
    float vx = ax + self.x * dv2 + b2.x;
    float vy = ay + self.y * dv2 + b2.y;
    vx = (vx >= 0.f) ? vx : 0.2f * vx;
    vy = (vy >= 0.f) ? vy : 0.2f * vy;
    __nv_bfloat16 hx = __float2bfloat16(vx), hy = __float2bfloat16(vy);
    size_t idx = (size_t)v * 256 + 2 * t;
    *(__nv_bfloat162*)&ohi[idx] = __nv_bfloat162(hx, hy);
    *(__nv_bfloat162*)&olo[idx] =
        __nv_bfloat162(__float2bfloat16(vx - __bfloat162float(hx)),
                       __float2bfloat16(vy - __bfloat162float(hy)));
}

// ---------------- agg layer-2: F=128, 2 nodes/block (64 thr each), half2 ------
__global__ void agg2_kernel(const __half* __restrict__ xw, const float* __restrict__ bias,
                            float* __restrict__ out, int r) {
    int g = threadIdx.x >> 6;           // 0 or 1 (warp-pair group)
    int q = threadIdx.x & 63;           // half2 lane: features 2q, 2q+1
    int v = blockIdx.x * 2 + g;
    const int2* pk = &g_csr_pk[r * EE];
    const __half2* xw2 = (const __half2*)xw;  // rows of 64 half2

    int beg = g_rowptr[r * (NN + 1) + v], end = g_rowptr[r * (NN + 1) + v + 1];
    float ax = 0.f, ay = 0.f;
    int e = beg;
    for (; e + 4 <= end; e += 4) {
        int2 p0 = __ldg(&pk[e]), p1 = __ldg(&pk[e + 1]);
        int2 p2 = __ldg(&pk[e + 2]), p3 = __ldg(&pk[e + 3]);
        __half2 g0 = __ldg(&xw2[(size_t)p0.x * 64 + q]);
        __half2 g1 = __ldg(&xw2[(size_t)p1.x * 64 + q]);
        __half2 g2 = __ldg(&xw2[(size_t)p2.x * 64 + q]);
        __half2 g3 = __ldg(&xw2[(size_t)p3.x * 64 + q]);
        float c0 = __int_as_float(p0.y), c1 = __int_as_float(p1.y);
        float c2 = __int_as_float(p2.y), c3 = __int_as_float(p3.y);
        float2 f0 = __half22float2(g0), f1 = __half22float2(g1);
        float2 f2 = __half22float2(g2), f3 = __half22float2(g3);
        ax += c0 * f0.x + c1 * f1.x + c2 * f2.x + c3 * f3.x;
        ay += c0 * f0.y + c1 * f1.y + c2 * f2.y + c3 * f3.y;
    }
    for (; e < end; e++) {
        int2 p = __ldg(&pk[e]);
        float c = __int_as_float(p.y);
        float2 f = __half22float2(__ldg(&xw2[(size_t)p.x * 64 + q]));
        ax += c * f.x;
        ay += c * f.y;
    }
    float dv = g_dinv[r * NN + v];
    float dv2 = dv * dv;
    float2 self = __half22float2(xw2[(size_t)v * 64 + q]);
    float2 b2 = *(const float2*)&bias[2 * q];
    float vx = ax + self.x * dv2 + b2.x;
    float vy = ay + self.y * dv2 + b2.y;
    vx = (vx >= 0.f) ? vx : 0.2f * vx;
    vy = (vy >= 0.f) ? vy : 0.2f * vy;
    *(float2*)&out[(size_t)v * 128 + 2 * q] = make_float2(vx, vy);
}

// ---------------- launch ------------------------------------------------------
extern "C" void kernel_launch(void* const* d_in, const int* in_sizes, int n_in,
                              void* d_out, int out_size) {
    const float* x[4] = {(const float*)d_in[0], (const float*)d_in[1],
                         (const float*)d_in[2], (const float*)d_in[3]};
    const void* ed[4] = {d_in[4], d_in[5], d_in[6], d_in[7]};
    const float* W1[4] = {(const float*)d_in[8], (const float*)d_in[10],
                          (const float*)d_in[16], (const float*)d_in[18]};
    const float* B1[4] = {(const float*)d_in[9], (const float*)d_in[11],
                          (const float*)d_in[17], (const float*)d_in[19]};
    const float* W2[4] = {(const float*)d_in[12], (const float*)d_in[14],
                          (const float*)d_in[20], (const float*)d_in[22]};
    const float* B2[4] = {(const float*)d_in[13], (const float*)d_in[15],
                          (const float*)d_in[21], (const float*)d_in[23]};
    float* out = (float*)d_out;

    __half *xw1b, *xw2b;
    __nv_bfloat16 *xhi, *xlo, *hhib, *hlob, *whi, *wlo;
    cudaGetSymbolAddress((void**)&xw1b, g_xw1);
    cudaGetSymbolAddress((void**)&xw2b, g_xw2);
    cudaGetSymbolAddress((void**)&xhi, g_Xhi);
    cudaGetSymbolAddress((void**)&xlo, g_Xlo);
    cudaGetSymbolAddress((void**)&hhib, g_Hhi);
    cudaGetSymbolAddress((void**)&hlob, g_Hlo);
    cudaGetSymbolAddress((void**)&whi, g_Whi);
    cudaGetSymbolAddress((void**)&wlo, g_Wlo);

    cudaFuncSetAttribute(gemm_mma, cudaFuncAttributeMaxDynamicSharedMemorySize, SMB_GEMM);

    // EXACTLY 3 plain streams (leak-free proven config)
    static cudaStream_t s1 = nullptr, s2 = nullptr, s3 = nullptr;
    static cudaEvent_t evRoot = nullptr, evConv = nullptr, evCSR = nullptr;
    static cudaEvent_t evS2 = nullptr, evS3 = nullptr, evS1J = nullptr;
    if (!s1) {
        cudaStreamCreateWithFlags(&s1, cudaStreamNonBlocking);
        cudaStreamCreateWithFlags(&s2, cudaStreamNonBlocking);
        cudaStreamCreateWithFlags(&s3, cudaStreamNonBlocking);
        cudaEventCreateWithFlags(&evRoot, cudaEventDisableTiming);
        cudaEventCreateWithFlags(&evConv, cudaEventDisableTiming);
        cudaEventCreateWithFlags(&evCSR, cudaEventDisableTiming);
        cudaEventCreateWithFlags(&evS2, cudaEventDisableTiming);
        cudaEventCreateWithFlags(&evS3, cudaEventDisableTiming);
        cudaEventCreateWithFlags(&evS1J, cudaEventDisableTiming);
    }

    // ---- fork: CSR chain onto s3 ----
    cudaEventRecord(evRoot, 0);
    cudaStreamWaitEvent(s3, evRoot, 0);
    detect_kernel<<<1, 32, 0, s3>>>(ed[0], ed[1], ed[2], ed[3]);
    zero_counts<<<(4 * NN + 255) / 256, 256, 0, s3>>>();
    build_deg<<<dim3((EE + 255) / 256, 4), 256, 0, s3>>>(ed[0], ed[1], ed[2], ed[3]);
    calc_dinv<<<(4 * NN + 255) / 256, 256, 0, s3>>>();
    scan_p1<<<dim3(NCHUNK, 4), CHUNK, 0, s3>>>();
    scan_p2<<<4, 128, 0, s3>>>();
    scan_p3<<<dim3(NCHUNK, 4), CHUNK, 0, s3>>>();
    build_csr<<<dim3((EE + 255) / 256, 4), 256, 0, s3>>>(ed[0], ed[1], ed[2], ed[3]);
    cudaEventRecord(evCSR, s3);

    // ---- conversions on stream 0 ----
    WArgs wa;
    for (int p = 0; p < 4; p++) {
        wa.W[p] = W1[p];     wa.N[p] = 256;     wa.off[p] = WOFF1(p);
        wa.W[4 + p] = W2[p]; wa.N[4 + p] = 128; wa.off[4 + p] = WOFF2(p);
    }
    wa.W[8] = (const float*)d_in[24]; wa.N[8] = 128; wa.off[8] = WOFFR(0);
    wa.W[9] = (const float*)d_in[26]; wa.N[9] = 128; wa.off[9] = WOFFR(1);
    convW10<<<dim3(256, 10), 256>>>(wa, whi, wlo);
    const int n4 = NN * 256 / 4;
    convA4<<<dim3((n4 + 255) / 256, 4), 256>>>(x[0], x[1], x[2], x[3], xhi, xlo, n4);
    cudaEventRecord(evConv, 0);
    cudaStreamWaitEvent(s1, evConv, 0);
    cudaStreamWaitEvent(s2, evConv, 0);
    cudaStreamWaitEvent(s3, evConv, 0);

    dim3 g1(4, (NN + 127) / 128);   // Ntot=256
    dim3 g2(2, (NN + 127) / 128);   // Ntot=128
    const size_t XSZ = (size_t)NN * 256;
    const size_t X2SZ = (size_t)NN * 128;

    cudaStream_t ps[4] = {(cudaStream_t)0, s1, s2, s3};
    for (int p = 0; p < 4; p++) {
        cudaStream_t st = ps[p];
        gemm_mma<<<g1, 256, SMB_GEMM, st>>>(xhi + p * XSZ, xlo + p * XSZ, whi + WOFF1(p),
                                            wlo + WOFF1(p), nullptr, xw1b + p * XSZ,
                                            NN, 256, nullptr, nullptr, nullptr, 0);
        if (p != 3) cudaStreamWaitEvent(st, evCSR, 0);  // s3 already ordered after CSR
        agg1_kernel<<<NN, 128, 0, st>>>(xw1b + p * XSZ, B1[p], hhib + p * XSZ,
                                        hlob + p * XSZ, p);
        gemm_mma<<<g2, 256, SMB_GEMM, st>>>(hhib + p * XSZ, hlob + p * XSZ, whi + WOFF2(p),
                                            wlo + WOFF2(p), nullptr, xw2b + p * X2SZ,
                                            NN, 128, nullptr, nullptr, nullptr, 0);
        agg2_kernel<<<NN / 2, 128, 0, st>>>(xw2b + p * X2SZ, B2[p],
                                            out + (size_t)(2 + p) * REGSZ, p);
    }

    // ---- join + residual/combine GEMMs ----
    cudaEventRecord(evS2, s2);
    cudaStreamWaitEvent(0, evS2, 0);
    gemm_mma<<<g2, 256, SMB_GEMM>>>(xhi, xlo, whi + WOFFR(0), wlo + WOFFR(0), out, nullptr,
                                    NN, 128, (const float*)d_in[25], out + (size_t)2 * REGSZ,
                                    out + (size_t)4 * REGSZ, 1);
    cudaEventRecord(evS3, s3);
    cudaStreamWaitEvent(s1, evS3, 0);
    gemm_mma<<<g2, 256, SMB_GEMM, s1>>>(xhi + XSZ, xlo + XSZ, whi + WOFFR(1), wlo + WOFFR(1),
                                        out + (size_t)REGSZ, nullptr, NN, 128,
                                        (const float*)d_in[27], out + (size_t)3 * REGSZ,
                                        out + (size_t)5 * REGSZ, 1);
    cudaEventRecord(evS1J, s1);
    cudaStreamWaitEvent(0, evS1J, 0);
}

// round 16
// speedup vs baseline: 1.2327x; 1.1303x over previous
#include <cuda_runtime.h>
#include <cuda_bf16.h>
#include <cuda_fp16.h>
#include <cstdint>

#define NN 50000
#define EE 800000
#define REGSZ (NN * 128)
#define CHUNK 512
#define NCHUNK ((NN + CHUNK - 1) / CHUNK)   // 98

// ---------------- scratch (static device globals; no runtime alloc) ----------
__device__ int   g_deg[4 * NN];
__device__ int   g_cursor[4 * NN];
__device__ int   g_rowptr[4 * (NN + 1)];
__device__ float g_dinv[4 * NN];
__device__ int2  g_csr_pk[4 * EE];          // packed {src, coef-as-int}
__device__ int   g_is64[4];
__device__ int   g_chunksum[4 * NCHUNK];
__device__ int   g_chunkoff[4 * NCHUNK];
// fp16 activations: inputs, hidden, GEMM outputs
__device__ __half g_Xh[4][NN * 256];
__device__ __half g_Hh[4][NN * 256];
__device__ __half g_xw1[4][NN * 256];
__device__ __half g_xw2[4][NN * 128];
// weights transposed [n][k], fp16 hi/lo split
#define WOFF1(p) ((p) * 65536)
#define WOFF2(p) (262144 + (p) * 32768)
#define WOFFR(i) (393216 + (i) * 32768)
__device__ __half g_Whi[458752];
__device__ __half g_Wlo[458752];

// ---------------- mma.sync / cp.async helpers --------------------------------
__device__ __forceinline__ uint32_t smem_u32(const void* p) {
    uint32_t a;
    asm("{ .reg .u64 t; cvta.to.shared.u64 t, %1; cvt.u32.u64 %0, t; }" : "=r"(a) : "l"(p));
    return a;
}
__device__ __forceinline__ void ldsm4(uint32_t& r0, uint32_t& r1, uint32_t& r2, uint32_t& r3,
                                      uint32_t a) {
    asm volatile("ldmatrix.sync.aligned.m8n8.x4.shared.b16 {%0,%1,%2,%3}, [%4];"
                 : "=r"(r0), "=r"(r1), "=r"(r2), "=r"(r3) : "r"(a));
}
__device__ __forceinline__ void mma16816h(float* d, const uint32_t* a, const uint32_t* b) {
    asm volatile(
        "mma.sync.aligned.m16n8k16.row.col.f32.f16.f16.f32 "
        "{%0,%1,%2,%3}, {%4,%5,%6,%7}, {%8,%9}, {%0,%1,%2,%3};"
        : "+f"(d[0]), "+f"(d[1]), "+f"(d[2]), "+f"(d[3])
        : "r"(a[0]), "r"(a[1]), "r"(a[2]), "r"(a[3]), "r"(b[0]), "r"(b[1]));
}
__device__ __forceinline__ void cp16(uint32_t dst, const void* src, bool pred) {
    int sz = pred ? 16 : 0;
    asm volatile("cp.async.ca.shared.global [%0], [%1], 16, %2;"
                 :: "r"(dst), "l"(src), "r"(sz) : "memory");
}
#define CP_COMMIT() asm volatile("cp.async.commit_group;" ::: "memory")

// ---------------- edge dtype sniffing + decode -------------------------------
__global__ void detect_kernel(const void* e0, const void* e1, const void* e2, const void* e3) {
    if (threadIdx.x < 4) {
        const void* p = threadIdx.x == 0 ? e0 : threadIdx.x == 1 ? e1 : threadIdx.x == 2 ? e2 : e3;
        const unsigned int* u = (const unsigned int*)p;
        unsigned int acc = 0;
        for (int i = 0; i < 64; i++) acc |= u[2 * i + 1];
        g_is64[threadIdx.x] = (acc == 0) ? 1 : 0;
    }
}

__device__ __forceinline__ int2 load_edge(const void* ep, int is64, int e) {
    int s, d;
    if (is64) {
        const long long* p = (const long long*)ep;
        s = (int)p[e];
        d = (int)p[EE + e];
    } else {
        const int* p = (const int*)ep;
        s = p[e];
        d = p[EE + e];
    }
    return make_int2(s, d);
}

// ---------------- CSR build ---------------------------------------------------
__global__ void zero_counts() {
    int i = blockIdx.x * blockDim.x + threadIdx.x;
    if (i < 4 * NN) { g_deg[i] = 0; g_cursor[i] = 0; }
}

__global__ void build_deg(const void* e0, const void* e1, const void* e2, const void* e3) {
    int e = blockIdx.x * blockDim.x + threadIdx.x;
    int r = blockIdx.y;
    if (e >= EE) return;
    const void* ep = r == 0 ? e0 : r == 1 ? e1 : r == 2 ? e2 : e3;
    int2 sd = load_edge(ep, g_is64[r], e);
    atomicAdd(&g_deg[r * NN + sd.y], 1);
}

__global__ void calc_dinv() {
    int i = blockIdx.x * blockDim.x + threadIdx.x;
    if (i < 4 * NN) g_dinv[i] = rsqrtf((float)g_deg[i] + 1.0f);
}

__global__ void scan_p1() {
    int r = blockIdx.y;
    int i = blockIdx.x * CHUNK + threadIdx.x;
    int v = (i < NN) ? g_deg[r * NN + i] : 0;
    __shared__ int sh[CHUNK];
    sh[threadIdx.x] = v;
    __syncthreads();
    for (int off = CHUNK / 2; off > 0; off >>= 1) {
        if (threadIdx.x < off) sh[threadIdx.x] += sh[threadIdx.x + off];
        __syncthreads();
    }
    if (threadIdx.x == 0) g_chunksum[r * NCHUNK + blockIdx.x] = sh[0];
}

__global__ void scan_p2() {
    int r = blockIdx.x;
    __shared__ int sh[128];
    int v = (threadIdx.x < NCHUNK) ? g_chunksum[r * NCHUNK + threadIdx.x] : 0;
    sh[threadIdx.x] = v;
    __syncthreads();
    for (int off = 1; off < 128; off <<= 1) {
        int t = (threadIdx.x >= off) ? sh[threadIdx.x - off] : 0;
        __syncthreads();
        sh[threadIdx.x] += t;
        __syncthreads();
    }
    if (threadIdx.x < NCHUNK) g_chunkoff[r * NCHUNK + threadIdx.x] = sh[threadIdx.x] - v;
    if (threadIdx.x == 127) g_rowptr[r * (NN + 1) + NN] = sh[127];
}

__global__ void scan_p3() {
    int r = blockIdx.y;
    int i = blockIdx.x * CHUNK + threadIdx.x;
    int v = (i < NN) ? g_deg[r * NN + i] : 0;
    __shared__ int sh[CHUNK];
    sh[threadIdx.x] = v;
    __syncthreads();
    for (int off = 1; off < CHUNK; off <<= 1) {
        int t = (threadIdx.x >= off) ? sh[threadIdx.x - off] : 0;
        __syncthreads();
        sh[threadIdx.x] += t;
        __syncthreads();
    }
    if (i < NN)
        g_rowptr[r * (NN + 1) + i] = g_chunkoff[r * NCHUNK + blockIdx.x] + sh[threadIdx.x] - v;
}

__global__ void build_csr(const void* e0, const void* e1, const void* e2, const void* e3) {
    int e = blockIdx.x * blockDim.x + threadIdx.x;
    int r = blockIdx.y;
    if (e >= EE) return;
    const void* ep = r == 0 ? e0 : r == 1 ? e1 : r == 2 ? e2 : e3;
    int2 sd = load_edge(ep, g_is64[r], e);
    int pos = g_rowptr[r * (NN + 1) + sd.y] + atomicAdd(&g_cursor[r * NN + sd.y], 1);
    float coef = g_dinv[r * NN + sd.x] * g_dinv[r * NN + sd.y];
    g_csr_pk[r * EE + pos] = make_int2(sd.x, __float_as_int(coef));
}

// ---------------- conversions (batched) ----------------------------------------
// inputs: fp32 -> single fp16
__global__ void convA4(const float* __restrict__ x0, const float* __restrict__ x1,
                       const float* __restrict__ x2, const float* __restrict__ x3,
                       __half* __restrict__ xh, int n4) {
    int i = blockIdx.x * 256 + threadIdx.x;
    if (i >= n4) return;
    int p = blockIdx.y;
    const float* x = p == 0 ? x0 : p == 1 ? x1 : p == 2 ? x2 : x3;
    size_t off = (size_t)p * NN * 256;
    float4 v = ((const float4*)x)[i];
    __half2* hp = (__half2*)&xh[off + (size_t)i * 4];
    hp[0] = __floats2half2_rn(v.x, v.y);
    hp[1] = __floats2half2_rn(v.z, v.w);
}

// weights: fp32 -> fp16 hi + fp16 lo (exact to ~2^-22)
struct WArgs {
    const float* W[10];
    int N[10];
    int off[10];
};
__global__ void convW10(WArgs a, __half* __restrict__ hi, __half* __restrict__ lo) {
    int m = blockIdx.y;
    int i = blockIdx.x * 256 + threadIdx.x;
    int N = a.N[m];
    if (i >= N * 256) return;
    int n = i >> 8, k = i & 255;
    float v = a.W[m][k * N + n];
    __half h = __float2half_rn(v);
    hi[a.off[m] + i] = h;
    lo[a.off[m] + i] = __float2half_rn(v - __half2float(h));
}

// ---------------- fp16 mma GEMM, 3-stage cp.async K32 pipeline ----------------
// A single fp16; B fp16 hi/lo split. 2 MMAs per fragment pair.
#define KC 32
#define LDA 40
#define S_A 0
#define S_BHI (128 * LDA)
#define S_BLO (128 * LDA + 64 * LDA)
#define STG_E (128 * LDA + 2 * 64 * LDA)       // 10240 elems = 20480 B/stage
#define NSTG 3
#define SMB_GEMM (NSTG * STG_E * 2)            // 61440 B

__global__ void __launch_bounds__(256, 2) gemm_mma(
    const __half* __restrict__ A,
    const __half* __restrict__ Bhi, const __half* __restrict__ Blo,
    float* __restrict__ C, __half* __restrict__ Ch, int M, int Ntot,
    const float* __restrict__ bias, const float* __restrict__ P,
    const float* __restrict__ Q, int comb) {
    extern __shared__ __half sm[];
    uint32_t sb = smem_u32(sm);
    int tid = threadIdx.x, lane = tid & 31, w = tid >> 5;
    int wm = w & 3, wn = w >> 2;
    int m0 = blockIdx.y * 128, n0 = blockIdx.x * 64;

    float acc[2][4][4];
#pragma unroll
    for (int mi = 0; mi < 2; mi++)
#pragma unroll
        for (int ni = 0; ni < 4; ni++)
#pragma unroll
            for (int q = 0; q < 4; q++) acc[mi][ni][q] = 0.0f;

    // A staging: row = tid>>1 (0..127), col group = (tid&1)*16 (+0,+8)
    int a_row = tid >> 1;
    int a_col = (tid & 1) * 16;
    bool a_ok = (m0 + a_row) < M;
    int a_src_row = a_ok ? (m0 + a_row) : (M - 1);
    // B staging: row = tid>>2 (0..63), col = (tid&3)*8
    int b_row = tid >> 2;
    int b_col = (tid & 3) * 8;

    uint32_t a_off[2], b_off[2];
#pragma unroll
    for (int mi = 0; mi < 2; mi++)
        a_off[mi] = (uint32_t)((wm * 32 + mi * 16 + (lane & 15)) * LDA + (lane >> 4) * 8);
#pragma unroll
    for (int bt = 0; bt < 2; bt++)
        b_off[bt] = (uint32_t)((wn * 32 + bt * 16 + ((lane >> 4) << 3) + (lane & 7)) * LDA +
                               ((lane >> 3) & 1) * 8);

    auto issue = [&](int c) {
        int k0 = c * KC;
        uint32_t base = sb + (uint32_t)((c % NSTG) * STG_E * 2);
        cp16(base + (uint32_t)((S_A + a_row * LDA + a_col) * 2),
             &A[(size_t)a_src_row * 256 + k0 + a_col], a_ok);
        cp16(base + (uint32_t)((S_A + a_row * LDA + a_col + 8) * 2),
             &A[(size_t)a_src_row * 256 + k0 + a_col + 8], a_ok);
        cp16(base + (uint32_t)((S_BHI + b_row * LDA + b_col) * 2),
             &Bhi[(size_t)(n0 + b_row) * 256 + k0 + b_col], true);
        cp16(base + (uint32_t)((S_BLO + b_row * LDA + b_col) * 2),
             &Blo[(size_t)(n0 + b_row) * 256 + k0 + b_col], true);
        CP_COMMIT();
    };

    issue(0);
    issue(1);

#pragma unroll
    for (int c = 0; c < 8; c++) {
        if (c < 7) asm volatile("cp.async.wait_group 1;" ::: "memory");
        else       asm volatile("cp.async.wait_group 0;" ::: "memory");
        __syncthreads();
        if (c + 2 < 8) issue(c + 2);

        uint32_t base = sb + (uint32_t)((c % NSTG) * STG_E * 2);
#pragma unroll
        for (int ks = 0; ks < 2; ks++) {
            int k = ks * 16;
            uint32_t aF[2][4], bH[4][2], bL[4][2];
#pragma unroll
            for (int mi = 0; mi < 2; mi++)
                ldsm4(aF[mi][0], aF[mi][1], aF[mi][2], aF[mi][3],
                      base + ((S_A + a_off[mi] + k) << 1));
#pragma unroll
            for (int bt = 0; bt < 2; bt++) {
                uint32_t r0, r1, r2, r3;
                ldsm4(r0, r1, r2, r3, base + ((S_BHI + b_off[bt] + k) << 1));
                bH[bt * 2][0] = r0; bH[bt * 2][1] = r1;
                bH[bt * 2 + 1][0] = r2; bH[bt * 2 + 1][1] = r3;
                ldsm4(r0, r1, r2, r3, base + ((S_BLO + b_off[bt] + k) << 1));
                bL[bt * 2][0] = r0; bL[bt * 2][1] = r1;
                bL[bt * 2 + 1][0] = r2; bL[bt * 2 + 1][1] = r3;
            }
#pragma unroll
            for (int mi = 0; mi < 2; mi++)
#pragma unroll
                for (int ni = 0; ni < 4; ni++) {
                    mma16816h(acc[mi][ni], aF[mi], bH[ni]);
                    mma16816h(acc[mi][ni], aF[mi], bL[ni]);
                }
        }
    }

#pragma unroll
    for (int mi = 0; mi < 2; mi++) {
#pragma unroll
        for (int ni = 0; ni < 4; ni++) {
            int col = n0 + wn * 32 + ni * 8 + (lane & 3) * 2;
            int r_lo = m0 + wm * 32 + mi * 16 + (lane >> 2);
            int r_hi = r_lo + 8;
#pragma unroll
            for (int half = 0; half < 2; half++) {
                int row = half ? r_hi : r_lo;
                if (row >= M) continue;
                float2 o;
                o.x = acc[mi][ni][half * 2 + 0];
                o.y = acc[mi][ni][half * 2 + 1];
                size_t base = (size_t)row * Ntot + col;
                if (Ch) {
                    *(__half2*)&Ch[base] = __floats2half2_rn(o.x, o.y);
                } else {
                    if (comb) {
                        o.x += bias[col] + 0.5f * (P[base] + Q[base]);
                        o.y += bias[col + 1] + 0.5f * (P[base + 1] + Q[base + 1]);
                    }
                    *(float2*)&C[base] = o;
                }
            }
        }
    }
}

// ---------------- agg layer-1: F=256, 128 thr/node, half2 gathers, unroll-4 ---
// output: single fp16 h (next GEMM's A)
__global__ void agg1_kernel(const __half* __restrict__ xw, const float* __restrict__ bias,
                            __half* __restrict__ oh, int r) {
    int v = blockIdx.x;
    int t = threadIdx.x;
    const int2* pk = &g_csr_pk[r * EE];
    const __half2* xw2 = (const __half2*)xw;

    int beg = g_rowptr[r * (NN + 1) + v], end = g_rowptr[r * (NN + 1) + v + 1];
    float ax = 0.f, ay = 0.f;
    int e = beg;
    for (; e + 4 <= end; e += 4) {
        int2 p0 = __ldg(&pk[e]), p1 = __ldg(&pk[e + 1]);
        int2 p2 = __ldg(&pk[e + 2]), p3 = __ldg(&pk[e + 3]);
        __half2 g0 = __ldg(&xw2[(size_t)p0.x * 128 + t]);
        __half2 g1 = __ldg(&xw2[(size_t)p1.x * 128 + t]);
        __half2 g2 = __ldg(&xw2[(size_t)p2.x * 128 + t]);
        __half2 g3 = __ldg(&xw2[(size_t)p3.x * 128 + t]);
        float c0 = __int_as_float(p0.y), c1 = __int_as_float(p1.y);
        float c2 = __int_as_float(p2.y), c3 = __int_as_float(p3.y);
        float2 f0 = __half22float2(g0), f1 = __half22float2(g1);
        float2 f2 = __half22float2(g2), f3 = __half22float2(g3);
        ax += c0 * f0.x + c1 * f1.x + c2 * f2.x + c3 * f3.x;
        ay += c0 * f0.y + c1 * f1.y + c2 * f2.y + c3 * f3.y;
    }
    for (; e < end; e++) {
        int2 p = __ldg(&pk[e]);
        float c = __int_as_float(p.y);
        float2 f = __half22float2(__ldg(&xw2[(size_t)p.x * 128 + t]));
        ax += c * f.x;
        ay += c * f.y;
    }
    float dv = g_dinv[r * NN + v];
    float dv2 = dv * dv;
    float2 self = __half22float2(xw2[(size_t)v * 128 + t]);
    float2 b2 = *(const float2*)&bias[2 * t];
    float vx = ax + self.x * dv2 + b2.x;
    float vy = ay + self.y * dv2 + b2.y;
    vx = (vx >= 0.f) ? vx : 0.2f * vx;
    vy = (vy >= 0.f) ? vy : 0.2f * vy;
    *(__half2*)&oh[(size_t)v * 256 + 2 * t] = __floats2half2_rn(vx, vy);
}

// ---------------- agg layer-2: F=128, 2 nodes/block (64 thr each), half2 ------
__global__ void agg2_kernel(const __half* __restrict__ xw, const float* __restrict__ bias,
                            float* __restrict__ out, int r) {
    int g = threadIdx.x >> 6;
    int q = threadIdx.x & 63;
    int v = blockIdx.x * 2 + g;
    const int2* pk = &g_csr_pk[r * EE];
    const __half2* xw2 = (const __half2*)xw;

    int beg = g_rowptr[r * (NN + 1) + v], end = g_rowptr[r * (NN + 1) + v + 1];
    float ax = 0.f, ay = 0.f;
    int e = beg;
    for (; e + 4 <= end; e += 4) {
        int2 p0 = __ldg(&pk[e]), p1 = __ldg(&pk[e + 1]);
        int2 p2 = __ldg(&pk[e + 2]), p3 = __ldg(&pk[e + 3]);
        __half2 g0 = __ldg(&xw2[(size_t)p0.x * 64 + q]);
        __half2 g1 = __ldg(&xw2[(size_t)p1.x * 64 + q]);
        __half2 g2 = __ldg(&xw2[(size_t)p2.x * 64 + q]);
        __half2 g3 = __ldg(&xw2[(size_t)p3.x * 64 + q]);
        float c0 = __int_as_float(p0.y), c1 = __int_as_float(p1.y);
        float c2 = __int_as_float(p2.y), c3 = __int_as_float(p3.y);
        float2 f0 = __half22float2(g0), f1 = __half22float2(g1);
        float2 f2 = __half22float2(g2), f3 = __half22float2(g3);
        ax += c0 * f0.x + c1 * f1.x + c2 * f2.x + c3 * f3.x;
        ay += c0 * f0.y + c1 * f1.y + c2 * f2.y + c3 * f3.y;
    }
    for (; e < end; e++) {
        int2 p = __ldg(&pk[e]);
        float c = __int_as_float(p.y);
        float2 f = __half22float2(__ldg(&xw2[(size_t)p.x * 64 + q]));
        ax += c * f.x;
        ay += c * f.y;
    }
    float dv = g_dinv[r * NN + v];
    float dv2 = dv * dv;
    float2 self = __half22float2(xw2[(size_t)v * 64 + q]);
    float2 b2 = *(const float2*)&bias[2 * q];
    float vx = ax + self.x * dv2 + b2.x;
    float vy = ay + self.y * dv2 + b2.y;
    vx = (vx >= 0.f) ? vx : 0.2f * vx;
    vy = (vy >= 0.f) ? vy : 0.2f * vy;
    *(float2*)&out[(size_t)v * 128 + 2 * q] = make_float2(vx, vy);
}

// ---------------- launch ------------------------------------------------------
extern "C" void kernel_launch(void* const* d_in, const int* in_sizes, int n_in,
                              void* d_out, int out_size) {
    const float* x[4] = {(const float*)d_in[0], (const float*)d_in[1],
                         (const float*)d_in[2], (const float*)d_in[3]};
    const void* ed[4] = {d_in[4], d_in[5], d_in[6], d_in[7]};
    const float* W1[4] = {(const float*)d_in[8], (const float*)d_in[10],
                          (const float*)d_in[16], (const float*)d_in[18]};
    const float* B1[4] = {(const float*)d_in[9], (const float*)d_in[11],
                          (const float*)d_in[17], (const float*)d_in[19]};
    const float* W2[4] = {(const float*)d_in[12], (const float*)d_in[14],
                          (const float*)d_in[20], (const float*)d_in[22]};
    const float* B2[4] = {(const float*)d_in[13], (const float*)d_in[15],
                          (const float*)d_in[21], (const float*)d_in[23]};
    float* out = (float*)d_out;

    __half *xh, *hh, *xw1b, *xw2b, *whi, *wlo;
    cudaGetSymbolAddress((void**)&xh, g_Xh);
    cudaGetSymbolAddress((void**)&hh, g_Hh);
    cudaGetSymbolAddress((void**)&xw1b, g_xw1);
    cudaGetSymbolAddress((void**)&xw2b, g_xw2);
    cudaGetSymbolAddress((void**)&whi, g_Whi);
    cudaGetSymbolAddress((void**)&wlo, g_Wlo);

    cudaFuncSetAttribute(gemm_mma, cudaFuncAttributeMaxDynamicSharedMemorySize, SMB_GEMM);

    // EXACTLY 3 plain streams (leak-free proven config)
    static cudaStream_t s1 = nullptr, s2 = nullptr, s3 = nullptr;
    static cudaEvent_t evRoot = nullptr, evConv = nullptr, evCSR = nullptr;
    static cudaEvent_t evS2 = nullptr, evS3 = nullptr, evS1J = nullptr;
    if (!s1) {
        cudaStreamCreateWithFlags(&s1, cudaStreamNonBlocking);
        cudaStreamCreateWithFlags(&s2, cudaStreamNonBlocking);
        cudaStreamCreateWithFlags(&s3, cudaStreamNonBlocking);
        cudaEventCreateWithFlags(&evRoot, cudaEventDisableTiming);
        cudaEventCreateWithFlags(&evConv, cudaEventDisableTiming);
        cudaEventCreateWithFlags(&evCSR, cudaEventDisableTiming);
        cudaEventCreateWithFlags(&evS2, cudaEventDisableTiming);
        cudaEventCreateWithFlags(&evS3, cudaEventDisableTiming);
        cudaEventCreateWithFlags(&evS1J, cudaEventDisableTiming);
    }

    // ---- fork: CSR chain onto s3 ----
    cudaEventRecord(evRoot, 0);
    cudaStreamWaitEvent(s3, evRoot, 0);
    detect_kernel<<<1, 32, 0, s3>>>(ed[0], ed[1], ed[2], ed[3]);
    zero_counts<<<(4 * NN + 255) / 256, 256, 0, s3>>>();
    build_deg<<<dim3((EE + 255) / 256, 4), 256, 0, s3>>>(ed[0], ed[1], ed[2], ed[3]);
    calc_dinv<<<(4 * NN + 255) / 256, 256, 0, s3>>>();
    scan_p1<<<dim3(NCHUNK, 4), CHUNK, 0, s3>>>();
    scan_p2<<<4, 128, 0, s3>>>();
    scan_p3<<<dim3(NCHUNK, 4), CHUNK, 0, s3>>>();
    build_csr<<<dim3((EE + 255) / 256, 4), 256, 0, s3>>>(ed[0], ed[1], ed[2], ed[3]);
    cudaEventRecord(evCSR, s3);

    // ---- conversions on stream 0 ----
    WArgs wa;
    for (int p = 0; p < 4; p++) {
        wa.W[p] = W1[p];     wa.N[p] = 256;     wa.off[p] = WOFF1(p);
        wa.W[4 + p] = W2[p]; wa.N[4 + p] = 128; wa.off[4 + p] = WOFF2(p);
    }
    wa.W[8] = (const float*)d_in[24]; wa.N[8] = 128; wa.off[8] = WOFFR(0);
    wa.W[9] = (const float*)d_in[26]; wa.N[9] = 128; wa.off[9] = WOFFR(1);
    convW10<<<dim3(256, 10), 256>>>(wa, whi, wlo);
    const int n4 = NN * 256 / 4;
    convA4<<<dim3((n4 + 255) / 256, 4), 256>>>(x[0], x[1], x[2], x[3], xh, n4);
    cudaEventRecord(evConv, 0);
    cudaStreamWaitEvent(s1, evConv, 0);
    cudaStreamWaitEvent(s2, evConv, 0);
    cudaStreamWaitEvent(s3, evConv, 0);

    dim3 g1(4, (NN + 127) / 128);   // Ntot=256
    dim3 g2(2, (NN + 127) / 128);   // Ntot=128
    const size_t XSZ = (size_t)NN * 256;
    const size_t X2SZ = (size_t)NN * 128;

    cudaStream_t ps[4] = {(cudaStream_t)0, s1, s2, s3};
    for (int p = 0; p < 4; p++) {
        cudaStream_t st = ps[p];
        gemm_mma<<<g1, 256, SMB_GEMM, st>>>(xh + p * XSZ, whi + WOFF1(p), wlo + WOFF1(p),
                                            nullptr, xw1b + p * XSZ, NN, 256,
                                            nullptr, nullptr, nullptr, 0);
        if (p != 3) cudaStreamWaitEvent(st, evCSR, 0);  // s3 already ordered after CSR
        agg1_kernel<<<NN, 128, 0, st>>>(xw1b + p * XSZ, B1[p], hh + p * XSZ, p);
        gemm_mma<<<g2, 256, SMB_GEMM, st>>>(hh + p * XSZ, whi + WOFF2(p), wlo + WOFF2(p),
                                            nullptr, xw2b + p * X2SZ, NN, 128,
                                            nullptr, nullptr, nullptr, 0);
        agg2_kernel<<<NN / 2, 128, 0, st>>>(xw2b + p * X2SZ, B2[p],
                                            out + (size_t)(2 + p) * REGSZ, p);
    }

    // ---- join + residual/combine GEMMs ----
    cudaEventRecord(evS2, s2);
    cudaStreamWaitEvent(0, evS2, 0);
    gemm_mma<<<g2, 256, SMB_GEMM>>>(xh, whi + WOFFR(0), wlo + WOFFR(0), out, nullptr,
                                    NN, 128, (const float*)d_in[25], out + (size_t)2 * REGSZ,
                                    out + (size_t)4 * REGSZ, 1);
    cudaEventRecord(evS3, s3);
    cudaStreamWaitEvent(s1, evS3, 0);
    gemm_mma<<<g2, 256, SMB_GEMM, s1>>>(xh + XSZ, whi + WOFFR(1), wlo + WOFFR(1),
                                        out + (size_t)REGSZ, nullptr, NN, 128,
                                        (const float*)d_in[27], out + (size_t)3 * REGSZ,
                                        out + (size_t)5 * REGSZ, 1);
    cudaEventRecord(evS1J, s1);
    cudaStreamWaitEvent(0, evS1J, 0);
}

// round 17
// speedup vs baseline: 1.3123x; 1.0646x over previous
#include <cuda_runtime.h>
#include <cuda_bf16.h>
#include <cuda_fp16.h>
#include <cstdint>

#define NN 50000
#define EE 800000
#define REGSZ (NN * 128)
#define CHUNK 512
#define NCHUNK ((NN + CHUNK - 1) / CHUNK)   // 98

// ---------------- scratch (static device globals; no runtime alloc) ----------
__device__ int   g_deg[4 * NN];
__device__ int   g_cursor[4 * NN];
__device__ int   g_rowptr[4 * (NN + 1)];
__device__ float g_dinv[4 * NN];
__device__ int2  g_csr_pk[4 * EE];          // packed {src, coef-as-int}
__device__ int   g_is64[4];
__device__ int   g_chunksum[4 * NCHUNK];
__device__ int   g_chunkoff[4 * NCHUNK];
// fp16 activations: inputs, hidden, GEMM outputs
__device__ __half g_Xh[4][NN * 256];
__device__ __half g_Hh[4][NN * 256];
__device__ __half g_xw1[4][NN * 256];
__device__ __half g_xw2[4][NN * 128];
// weights transposed [n][k], single fp16
#define WOFF1(p) ((p) * 65536)
#define WOFF2(p) (262144 + (p) * 32768)
#define WOFFR(i) (393216 + (i) * 32768)
__device__ __half g_Wh[458752];

// ---------------- mma.sync / cp.async helpers --------------------------------
__device__ __forceinline__ uint32_t smem_u32(const void* p) {
    uint32_t a;
    asm("{ .reg .u64 t; cvta.to.shared.u64 t, %1; cvt.u32.u64 %0, t; }" : "=r"(a) : "l"(p));
    return a;
}
__device__ __forceinline__ void ldsm4(uint32_t& r0, uint32_t& r1, uint32_t& r2, uint32_t& r3,
                                      uint32_t a) {
    asm volatile("ldmatrix.sync.aligned.m8n8.x4.shared.b16 {%0,%1,%2,%3}, [%4];"
                 : "=r"(r0), "=r"(r1), "=r"(r2), "=r"(r3) : "r"(a));
}
__device__ __forceinline__ void mma16816h(float* d, const uint32_t* a, const uint32_t* b) {
    asm volatile(
        "mma.sync.aligned.m16n8k16.row.col.f32.f16.f16.f32 "
        "{%0,%1,%2,%3}, {%4,%5,%6,%7}, {%8,%9}, {%0,%1,%2,%3};"
        : "+f"(d[0]), "+f"(d[1]), "+f"(d[2]), "+f"(d[3])
        : "r"(a[0]), "r"(a[1]), "r"(a[2]), "r"(a[3]), "r"(b[0]), "r"(b[1]));
}
__device__ __forceinline__ void cp16(uint32_t dst, const void* src, bool pred) {
    int sz = pred ? 16 : 0;
    asm volatile("cp.async.ca.shared.global [%0], [%1], 16, %2;"
                 :: "r"(dst), "l"(src), "r"(sz) : "memory");
}
#define CP_COMMIT() asm volatile("cp.async.commit_group;" ::: "memory")

// ---------------- edge dtype sniffing + decode -------------------------------
__global__ void detect_kernel(const void* e0, const void* e1, const void* e2, const void* e3) {
    if (threadIdx.x < 4) {
        const void* p = threadIdx.x == 0 ? e0 : threadIdx.x == 1 ? e1 : threadIdx.x == 2 ? e2 : e3;
        const unsigned int* u = (const unsigned int*)p;
        unsigned int acc = 0;
        for (int i = 0; i < 64; i++) acc |= u[2 * i + 1];
        g_is64[threadIdx.x] = (acc == 0) ? 1 : 0;
    }
}

__device__ __forceinline__ int2 load_edge(const void* ep, int is64, int e) {
    int s, d;
    if (is64) {
        const long long* p = (const long long*)ep;
        s = (int)p[e];
        d = (int)p[EE + e];
    } else {
        const int* p = (const int*)ep;
        s = p[e];
        d = p[EE + e];
    }
    return make_int2(s, d);
}

// ---------------- CSR build ---------------------------------------------------
__global__ void zero_counts() {
    int i = blockIdx.x * blockDim.x + threadIdx.x;
    if (i < 4 * NN) { g_deg[i] = 0; g_cursor[i] = 0; }
}

__global__ void build_deg(const void* e0, const void* e1, const void* e2, const void* e3) {
    int e = blockIdx.x * blockDim.x + threadIdx.x;
    int r = blockIdx.y;
    if (e >= EE) return;
    const void* ep = r == 0 ? e0 : r == 1 ? e1 : r == 2 ? e2 : e3;
    int2 sd = load_edge(ep, g_is64[r], e);
    atomicAdd(&g_deg[r * NN + sd.y], 1);
}

__global__ void calc_dinv() {
    int i = blockIdx.x * blockDim.x + threadIdx.x;
    if (i < 4 * NN) g_dinv[i] = rsqrtf((float)g_deg[i] + 1.0f);
}

__global__ void scan_p1() {
    int r = blockIdx.y;
    int i = blockIdx.x * CHUNK + threadIdx.x;
    int v = (i < NN) ? g_deg[r * NN + i] : 0;
    __shared__ int sh[CHUNK];
    sh[threadIdx.x] = v;
    __syncthreads();
    for (int off = CHUNK / 2; off > 0; off >>= 1) {
        if (threadIdx.x < off) sh[threadIdx.x] += sh[threadIdx.x + off];
        __syncthreads();
    }
    if (threadIdx.x == 0) g_chunksum[r * NCHUNK + blockIdx.x] = sh[0];
}

__global__ void scan_p2() {
    int r = blockIdx.x;
    __shared__ int sh[128];
    int v = (threadIdx.x < NCHUNK) ? g_chunksum[r * NCHUNK + threadIdx.x] : 0;
    sh[threadIdx.x] = v;
    __syncthreads();
    for (int off = 1; off < 128; off <<= 1) {
        int t = (threadIdx.x >= off) ? sh[threadIdx.x - off] : 0;
        __syncthreads();
        sh[threadIdx.x] += t;
        __syncthreads();
    }
    if (threadIdx.x < NCHUNK) g_chunkoff[r * NCHUNK + threadIdx.x] = sh[threadIdx.x] - v;
    if (threadIdx.x == 127) g_rowptr[r * (NN + 1) + NN] = sh[127];
}

__global__ void scan_p3() {
    int r = blockIdx.y;
    int i = blockIdx.x * CHUNK + threadIdx.x;
    int v = (i < NN) ? g_deg[r * NN + i] : 0;
    __shared__ int sh[CHUNK];
    sh[threadIdx.x] = v;
    __syncthreads();
    for (int off = 1; off < CHUNK; off <<= 1) {
        int t = (threadIdx.x >= off) ? sh[threadIdx.x - off] : 0;
        __syncthreads();
        sh[threadIdx.x] += t;
        __syncthreads();
    }
    if (i < NN)
        g_rowptr[r * (NN + 1) + i] = g_chunkoff[r * NCHUNK + blockIdx.x] + sh[threadIdx.x] - v;
}

__global__ void build_csr(const void* e0, const void* e1, const void* e2, const void* e3) {
    int e = blockIdx.x * blockDim.x + threadIdx.x;
    int r = blockIdx.y;
    if (e >= EE) return;
    const void* ep = r == 0 ? e0 : r == 1 ? e1 : r == 2 ? e2 : e3;
    int2 sd = load_edge(ep, g_is64[r], e);
    int pos = g_rowptr[r * (NN + 1) + sd.y] + atomicAdd(&g_cursor[r * NN + sd.y], 1);
    float coef = g_dinv[r * NN + sd.x] * g_dinv[r * NN + sd.y];
    g_csr_pk[r * EE + pos] = make_int2(sd.x, __float_as_int(coef));
}

// ---------------- conversions (batched) ----------------------------------------
__global__ void convA4(const float* __restrict__ x0, const float* __restrict__ x1,
                       const float* __restrict__ x2, const float* __restrict__ x3,
                       __half* __restrict__ xh, int n4) {
    int i = blockIdx.x * 256 + threadIdx.x;
    if (i >= n4) return;
    int p = blockIdx.y;
    const float* x = p == 0 ? x0 : p == 1 ? x1 : p == 2 ? x2 : x3;
    size_t off = (size_t)p * NN * 256;
    float4 v = ((const float4*)x)[i];
    __half2* hp = (__half2*)&xh[off + (size_t)i * 4];
    hp[0] = __floats2half2_rn(v.x, v.y);
    hp[1] = __floats2half2_rn(v.z, v.w);
}

struct WArgs {
    const float* W[10];
    int N[10];
    int off[10];
};
__global__ void convW10(WArgs a, __half* __restrict__ wh) {
    int m = blockIdx.y;
    int i = blockIdx.x * 256 + threadIdx.x;
    int N = a.N[m];
    if (i >= N * 256) return;
    int n = i >> 8, k = i & 255;
    wh[a.off[m] + i] = __float2half_rn(a.W[m][k * N + n]);
}

// ---------------- fp16 mma GEMM, 3-stage cp.async K32 pipeline ----------------
// A single fp16; B single fp16. 1 MMA per fragment pair.
#define KC 32
#define LDA 40
#define S_A 0
#define S_B (128 * LDA)
#define STG_E (128 * LDA + 64 * LDA)           // 7680 elems = 15360 B/stage
#define NSTG 3
#define SMB_GEMM (NSTG * STG_E * 2)            // 46080 B

__global__ void __launch_bounds__(256, 2) gemm_mma(
    const __half* __restrict__ A, const __half* __restrict__ B,
    float* __restrict__ C, __half* __restrict__ Ch, int M, int Ntot,
    const float* __restrict__ bias, const float* __restrict__ P,
    const float* __restrict__ Q, int comb) {
    extern __shared__ __half sm[];
    uint32_t sb = smem_u32(sm);
    int tid = threadIdx.x, lane = tid & 31, w = tid >> 5;
    int wm = w & 3, wn = w >> 2;
    int m0 = blockIdx.y * 128, n0 = blockIdx.x * 64;

    float acc[2][4][4];
#pragma unroll
    for (int mi = 0; mi < 2; mi++)
#pragma unroll
        for (int ni = 0; ni < 4; ni++)
#pragma unroll
            for (int q = 0; q < 4; q++) acc[mi][ni][q] = 0.0f;

    // A staging: row = tid>>1 (0..127), col group = (tid&1)*16 (+0,+8)
    int a_row = tid >> 1;
    int a_col = (tid & 1) * 16;
    bool a_ok = (m0 + a_row) < M;
    int a_src_row = a_ok ? (m0 + a_row) : (M - 1);
    // B staging: row = tid>>2 (0..63), col = (tid&3)*8
    int b_row = tid >> 2;
    int b_col = (tid & 3) * 8;

    uint32_t a_off[2], b_off[2];
#pragma unroll
    for (int mi = 0; mi < 2; mi++)
        a_off[mi] = (uint32_t)((wm * 32 + mi * 16 + (lane & 15)) * LDA + (lane >> 4) * 8);
#pragma unroll
    for (int bt = 0; bt < 2; bt++)
        b_off[bt] = (uint32_t)((wn * 32 + bt * 16 + ((lane >> 4) << 3) + (lane & 7)) * LDA +
                               ((lane >> 3) & 1) * 8);

    auto issue = [&](int c) {
        int k0 = c * KC;
        uint32_t base = sb + (uint32_t)((c % NSTG) * STG_E * 2);
        cp16(base + (uint32_t)((S_A + a_row * LDA + a_col) * 2),
             &A[(size_t)a_src_row * 256 + k0 + a_col], a_ok);
        cp16(base + (uint32_t)((S_A + a_row * LDA + a_col + 8) * 2),
             &A[(size_t)a_src_row * 256 + k0 + a_col + 8], a_ok);
        cp16(base + (uint32_t)((S_B + b_row * LDA + b_col) * 2),
             &B[(size_t)(n0 + b_row) * 256 + k0 + b_col], true);
        CP_COMMIT();
    };

    issue(0);
    issue(1);

#pragma unroll
    for (int c = 0; c < 8; c++) {
        if (c < 7) asm volatile("cp.async.wait_group 1;" ::: "memory");
        else       asm volatile("cp.async.wait_group 0;" ::: "memory");
        __syncthreads();
        if (c + 2 < 8) issue(c + 2);

        uint32_t base = sb + (uint32_t)((c % NSTG) * STG_E * 2);
#pragma unroll
        for (int ks = 0; ks < 2; ks++) {
            int k = ks * 16;
            uint32_t aF[2][4], bF[4][2];
#pragma unroll
            for (int mi = 0; mi < 2; mi++)
                ldsm4(aF[mi][0], aF[mi][1], aF[mi][2], aF[mi][3],
                      base + ((S_A + a_off[mi] + k) << 1));
#pragma unroll
            for (int bt = 0; bt < 2; bt++) {
                uint32_t r0, r1, r2, r3;
                ldsm4(r0, r1, r2, r3, base + ((S_B + b_off[bt] + k) << 1));
                bF[bt * 2][0] = r0; bF[bt * 2][1] = r1;
                bF[bt * 2 + 1][0] = r2; bF[bt * 2 + 1][1] = r3;
            }
#pragma unroll
            for (int mi = 0; mi < 2; mi++)
#pragma unroll
                for (int ni = 0; ni < 4; ni++)
                    mma16816h(acc[mi][ni], aF[mi], bF[ni]);
        }
    }

#pragma unroll
    for (int mi = 0; mi < 2; mi++) {
#pragma unroll
        for (int ni = 0; ni < 4; ni++) {
            int col = n0 + wn * 32 + ni * 8 + (lane & 3) * 2;
            int r_lo = m0 + wm * 32 + mi * 16 + (lane >> 2);
            int r_hi = r_lo + 8;
#pragma unroll
            for (int half = 0; half < 2; half++) {
                int row = half ? r_hi : r_lo;
                if (row >= M) continue;
                float2 o;
                o.x = acc[mi][ni][half * 2 + 0];
                o.y = acc[mi][ni][half * 2 + 1];
                size_t base = (size_t)row * Ntot + col;
                if (Ch) {
                    *(__half2*)&Ch[base] = __floats2half2_rn(o.x, o.y);
                } else {
                    if (comb) {
                        o.x += bias[col] + 0.5f * (P[base] + Q[base]);
                        o.y += bias[col + 1] + 0.5f * (P[base + 1] + Q[base + 1]);
                    }
                    *(float2*)&C[base] = o;
                }
            }
        }
    }
}

// ---------------- agg layer-1: F=256, 128 thr/node, half2 gathers, unroll-4 ---
__global__ void agg1_kernel(const __half* __restrict__ xw, const float* __restrict__ bias,
                            __half* __restrict__ oh, int r) {
    int v = blockIdx.x;
    int t = threadIdx.x;
    const int2* pk = &g_csr_pk[r * EE];
    const __half2* xw2 = (const __half2*)xw;

    int beg = g_rowptr[r * (NN + 1) + v], end = g_rowptr[r * (NN + 1) + v + 1];
    float ax = 0.f, ay = 0.f;
    int e = beg;
    for (; e + 4 <= end; e += 4) {
        int2 p0 = __ldg(&pk[e]), p1 = __ldg(&pk[e + 1]);
        int2 p2 = __ldg(&pk[e + 2]), p3 = __ldg(&pk[e + 3]);
        __half2 g0 = __ldg(&xw2[(size_t)p0.x * 128 + t]);
        __half2 g1 = __ldg(&xw2[(size_t)p1.x * 128 + t]);
        __half2 g2 = __ldg(&xw2[(size_t)p2.x * 128 + t]);
        __half2 g3 = __ldg(&xw2[(size_t)p3.x * 128 + t]);
        float c0 = __int_as_float(p0.y), c1 = __int_as_float(p1.y);
        float c2 = __int_as_float(p2.y), c3 = __int_as_float(p3.y);
        float2 f0 = __half22float2(g0), f1 = __half22float2(g1);
        float2 f2 = __half22float2(g2), f3 = __half22float2(g3);
        ax += c0 * f0.x + c1 * f1.x + c2 * f2.x + c3 * f3.x;
        ay += c0 * f0.y + c1 * f1.y + c2 * f2.y + c3 * f3.y;
    }
    for (; e < end; e++) {
        int2 p = __ldg(&pk[e]);
        float c = __int_as_float(p.y);
        float2 f = __half22float2(__ldg(&xw2[(size_t)p.x * 128 + t]));
        ax += c * f.x;
        ay += c * f.y;
    }
    float dv = g_dinv[r * NN + v];
    float dv2 = dv * dv;
    float2 self = __half22float2(xw2[(size_t)v * 128 + t]);
    float2 b2 = *(const float2*)&bias[2 * t];
    float vx = ax + self.x * dv2 + b2.x;
    float vy = ay + self.y * dv2 + b2.y;
    vx = (vx >= 0.f) ? vx : 0.2f * vx;
    vy = (vy >= 0.f) ? vy : 0.2f * vy;
    *(__half2*)&oh[(size_t)v * 256 + 2 * t] = __floats2half2_rn(vx, vy);
}

// ---------------- agg layer-2: F=128, 2 nodes/block (64 thr each), half2 ------
__global__ void agg2_kernel(const __half* __restrict__ xw, const float* __restrict__ bias,
                            float* __restrict__ out, int r) {
    int g = threadIdx.x >> 6;
    int q = threadIdx.x & 63;
    int v = blockIdx.x * 2 + g;
    const int2* pk = &g_csr_pk[r * EE];
    const __half2* xw2 = (const __half2*)xw;

    int beg = g_rowptr[r * (NN + 1) + v], end = g_rowptr[r * (NN + 1) + v + 1];
    float ax = 0.f, ay = 0.f;
    int e = beg;
    for (; e + 4 <= end; e += 4) {
        int2 p0 = __ldg(&pk[e]), p1 = __ldg(&pk[e + 1]);
        int2 p2 = __ldg(&pk[e + 2]), p3 = __ldg(&pk[e + 3]);
        __half2 g0 = __ldg(&xw2[(size_t)p0.x * 64 + q]);
        __half2 g1 = __ldg(&xw2[(size_t)p1.x * 64 + q]);
        __half2 g2 = __ldg(&xw2[(size_t)p2.x * 64 + q]);
        __half2 g3 = __ldg(&xw2[(size_t)p3.x * 64 + q]);
        float c0 = __int_as_float(p0.y), c1 = __int_as_float(p1.y);
        float c2 = __int_as_float(p2.y), c3 = __int_as_float(p3.y);
        float2 f0 = __half22float2(g0), f1 = __half22float2(g1);
        float2 f2 = __half22float2(g2), f3 = __half22float2(g3);
        ax += c0 * f0.x + c1 * f1.x + c2 * f2.x + c3 * f3.x;
        ay += c0 * f0.y + c1 * f1.y + c2 * f2.y + c3 * f3.y;
    }
    for (; e < end; e++) {
        int2 p = __ldg(&pk[e]);
        float c = __int_as_float(p.y);
        float2 f = __half22float2(__ldg(&xw2[(size_t)p.x * 64 + q]));
        ax += c * f.x;
        ay += c * f.y;
    }
    float dv = g_dinv[r * NN + v];
    float dv2 = dv * dv;
    float2 self = __half22float2(xw2[(size_t)v * 64 + q]);
    float2 b2 = *(const float2*)&bias[2 * q];
    float vx = ax + self.x * dv2 + b2.x;
    float vy = ay + self.y * dv2 + b2.y;
    vx = (vx >= 0.f) ? vx : 0.2f * vx;
    vy = (vy >= 0.f) ? vy : 0.2f * vy;
    *(float2*)&out[(size_t)v * 128 + 2 * q] = make_float2(vx, vy);
}

// ---------------- launch ------------------------------------------------------
extern "C" void kernel_launch(void* const* d_in, const int* in_sizes, int n_in,
                              void* d_out, int out_size) {
    const float* x[4] = {(const float*)d_in[0], (const float*)d_in[1],
                         (const float*)d_in[2], (const float*)d_in[3]};
    const void* ed[4] = {d_in[4], d_in[5], d_in[6], d_in[7]};
    const float* W1[4] = {(const float*)d_in[8], (const float*)d_in[10],
                          (const float*)d_in[16], (const float*)d_in[18]};
    const float* B1[4] = {(const float*)d_in[9], (const float*)d_in[11],
                          (const float*)d_in[17], (const float*)d_in[19]};
    const float* W2[4] = {(const float*)d_in[12], (const float*)d_in[14],
                          (const float*)d_in[20], (const float*)d_in[22]};
    const float* B2[4] = {(const float*)d_in[13], (const float*)d_in[15],
                          (const float*)d_in[21], (const float*)d_in[23]};
    float* out = (float*)d_out;

    __half *xh, *hh, *xw1b, *xw2b, *wh;
    cudaGetSymbolAddress((void**)&xh, g_Xh);
    cudaGetSymbolAddress((void**)&hh, g_Hh);
    cudaGetSymbolAddress((void**)&xw1b, g_xw1);
    cudaGetSymbolAddress((void**)&xw2b, g_xw2);
    cudaGetSymbolAddress((void**)&wh, g_Wh);

    cudaFuncSetAttribute(gemm_mma, cudaFuncAttributeMaxDynamicSharedMemorySize, SMB_GEMM);

    // EXACTLY 3 plain streams (leak-free proven config)
    static cudaStream_t s1 = nullptr, s2 = nullptr, s3 = nullptr;
    static cudaEvent_t evRoot = nullptr, evConv = nullptr, evCSR = nullptr;
    static cudaEvent_t evS2 = nullptr, evS3 = nullptr, evS1J = nullptr;
    if (!s1) {
        cudaStreamCreateWithFlags(&s1, cudaStreamNonBlocking);
        cudaStreamCreateWithFlags(&s2, cudaStreamNonBlocking);
        cudaStreamCreateWithFlags(&s3, cudaStreamNonBlocking);
        cudaEventCreateWithFlags(&evRoot, cudaEventDisableTiming);
        cudaEventCreateWithFlags(&evConv, cudaEventDisableTiming);
        cudaEventCreateWithFlags(&evCSR, cudaEventDisableTiming);
        cudaEventCreateWithFlags(&evS2, cudaEventDisableTiming);
        cudaEventCreateWithFlags(&evS3, cudaEventDisableTiming);
        cudaEventCreateWithFlags(&evS1J, cudaEventDisableTiming);
    }

    // ---- fork: CSR chain onto s3 ----
    cudaEventRecord(evRoot, 0);
    cudaStreamWaitEvent(s3, evRoot, 0);
    detect_kernel<<<1, 32, 0, s3>>>(ed[0], ed[1], ed[2], ed[3]);
    zero_counts<<<(4 * NN + 255) / 256, 256, 0, s3>>>();
    build_deg<<<dim3((EE + 255) / 256, 4), 256, 0, s3>>>(ed[0], ed[1], ed[2], ed[3]);
    calc_dinv<<<(4 * NN + 255) / 256, 256, 0, s3>>>();
    scan_p1<<<dim3(NCHUNK, 4), CHUNK, 0, s3>>>();
    scan_p2<<<4, 128, 0, s3>>>();
    scan_p3<<<dim3(NCHUNK, 4), CHUNK, 0, s3>>>();
    build_csr<<<dim3((EE + 255) / 256, 4), 256, 0, s3>>>(ed[0], ed[1], ed[2], ed[3]);
    cudaEventRecord(evCSR, s3);

    // ---- conversions on stream 0 ----
    WArgs wa;
    for (int p = 0; p < 4; p++) {
        wa.W[p] = W1[p];     wa.N[p] = 256;     wa.off[p] = WOFF1(p);
        wa.W[4 + p] = W2[p]; wa.N[4 + p] = 128; wa.off[4 + p] = WOFF2(p);
    }
    wa.W[8] = (const float*)d_in[24]; wa.N[8] = 128; wa.off[8] = WOFFR(0);
    wa.W[9] = (const float*)d_in[26]; wa.N[9] = 128; wa.off[9] = WOFFR(1);
    convW10<<<dim3(256, 10), 256>>>(wa, wh);
    const int n4 = NN * 256 / 4;
    convA4<<<dim3((n4 + 255) / 256, 4), 256>>>(x[0], x[1], x[2], x[3], xh, n4);
    cudaEventRecord(evConv, 0);
    cudaStreamWaitEvent(s1, evConv, 0);
    cudaStreamWaitEvent(s2, evConv, 0);
    cudaStreamWaitEvent(s3, evConv, 0);

    dim3 g1(4, (NN + 127) / 128);   // Ntot=256
    dim3 g2(2, (NN + 127) / 128);   // Ntot=128
    const size_t XSZ = (size_t)NN * 256;
    const size_t X2SZ = (size_t)NN * 128;

    cudaStream_t ps[4] = {(cudaStream_t)0, s1, s2, s3};
    for (int p = 0; p < 4; p++) {
        cudaStream_t st = ps[p];
        gemm_mma<<<g1, 256, SMB_GEMM, st>>>(xh + p * XSZ, wh + WOFF1(p), nullptr,
                                            xw1b + p * XSZ, NN, 256,
                                            nullptr, nullptr, nullptr, 0);
        if (p != 3) cudaStreamWaitEvent(st, evCSR, 0);  // s3 already ordered after CSR
        agg1_kernel<<<NN, 128, 0, st>>>(xw1b + p * XSZ, B1[p], hh + p * XSZ, p);
        gemm_mma<<<g2, 256, SMB_GEMM, st>>>(hh + p * XSZ, wh + WOFF2(p), nullptr,
                                            xw2b + p * X2SZ, NN, 128,
                                            nullptr, nullptr, nullptr, 0);
        agg2_kernel<<<NN / 2, 128, 0, st>>>(xw2b + p * X2SZ, B2[p],
                                            out + (size_t)(2 + p) * REGSZ, p);
    }

    // ---- join + residual/combine GEMMs ----
    cudaEventRecord(evS2, s2);
    cudaStreamWaitEvent(0, evS2, 0);
    gemm_mma<<<g2, 256, SMB_GEMM>>>(xh, wh + WOFFR(0), out, nullptr, NN, 128,
                                    (const float*)d_in[25], out + (size_t)2 * REGSZ,
                                    out + (size_t)4 * REGSZ, 1);
    cudaEventRecord(evS3, s3);
    cudaStreamWaitEvent(s1, evS3, 0);
    gemm_mma<<<g2, 256, SMB_GEMM, s1>>>(xh + XSZ, wh + WOFFR(1), out + (size_t)REGSZ,
                                        nullptr, NN, 128, (const float*)d_in[27],
                                        out + (size_t)3 * REGSZ, out + (size_t)5 * REGSZ, 1);
    cudaEventRecord(evS1J, s1);
    cudaStreamWaitEvent(0, evS1J, 0);
}